// round 4
// baseline (speedup 1.0000x reference)
#include <cuda_runtime.h>

#define CC 64
#define NPIX (512*512)
#define NL 8
#define SUBT 128
#define PITCH 68
#define PD 66
#define NTILE (NPIX/SUBT)
#define SBLK 74
#define APT 256
#define NATILE (NPIX/APT)
#define TSTRIDE 4100
#define NS_IT 6

// ---------------- global scratch (no runtime allocations) ----------------
__device__ float        g_S1[2][NL][CC];
__device__ unsigned int g_cnt[2][NL];
__device__ float        g_part[2][SBLK][NL*CC*CC];   // stats partials (staging)
__device__ float        g_S2[2][NL][CC*CC];
__device__ float        g_WC[2][NL][CC*CC];          // [0]=cov_c^{-1/2}, [1]=cov_s^{1/2}
__device__ float        g_mu[2][NL][CC];
__device__ float        g_T[NL][CC*CC];
__device__ float        g_beta[NL][CC];
__device__ int          g_valid[NL];

// ---------------- packed f32x2 helpers ----------------
typedef unsigned long long u64;

__device__ __forceinline__ u64 pk(float a, float b) {
    u64 r;
    asm("mov.b64 %0, {%1, %2};" : "=l"(r) : "r"(__float_as_uint(a)), "r"(__float_as_uint(b)));
    return r;
}
__device__ __forceinline__ float2 upk(u64 v) {
    unsigned int lo, hi;
    asm("mov.b64 {%0, %1}, %2;" : "=r"(lo), "=r"(hi) : "l"(v));
    return make_float2(__uint_as_float(lo), __uint_as_float(hi));
}
__device__ __forceinline__ u64 dupf(float a) {
    u64 r;
    asm("mov.b64 %0, {%1, %1};" : "=l"(r) : "r"(__float_as_uint(a)));
    return r;
}
#define FMA2(d, a, b) asm("fma.rn.f32x2 %0, %1, %2, %0;" : "+l"(d) : "l"(a), "l"(b))
#define ADD2(d, a, b) asm("add.rn.f32x2 %0, %1, %2;" : "=l"(d) : "l"(a), "l"(b))

__global__ void zero_kernel() {
    int i = threadIdx.x;
    float* p1 = &g_S1[0][0][0];
    for (int k = i; k < 2*NL*CC; k += 256) p1[k] = 0.f;
    if (i < 2*NL) (&g_cnt[0][0])[i] = 0u;
}

// ================= stats: per-label count, S1, S2 = X X^T (f32x2) =================
__global__ __launch_bounds__(256, 1)
void stats_kernel(const float* __restrict__ cf, const float* __restrict__ sf,
                  const int* __restrict__ cs, const int* __restrict__ ss) {
    extern __shared__ char smraw[];
    float* xt = (float*)smraw;                                   // [SUBT][PITCH]
    u64*   xd = (u64*)(smraw + SUBT*PITCH*4);                    // [SUBT][PD] dup-packed

    __shared__ unsigned short lst[NL][SUBT];
    __shared__ int cnt[NL];
    __shared__ float s1[NL][CC];
    __shared__ unsigned int gcnt[NL];

    int which = blockIdx.y;
    const float* feat = which ? sf : cf;
    const int*   seg  = which ? ss : cs;
    int tid = threadIdx.x;

    for (int k = tid; k < NL*CC; k += 256) (&s1[0][0])[k] = 0.f;
    if (tid < NL) gcnt[tid] = 0u;

    int rr = tid >> 4, cr = tid & 15;
    u64 acc[NL][8];
    #pragma unroll
    for (int l = 0; l < NL; l++)
        #pragma unroll
        for (int j = 0; j < 8; j++) acc[l][j] = 0ull;

    for (int t = blockIdx.x; t < NTILE; t += gridDim.x) {
        int base = t * SUBT;
        __syncthreads();
        if (tid < NL) cnt[tid] = 0;
        __syncthreads();
        if (tid < SUBT) {
            int lab = seg[base + tid] & 7;
            int pos = atomicAdd(&cnt[lab], 1);
            lst[lab][pos] = (unsigned short)tid;
        }
        #pragma unroll 4
        for (int k = tid; k < SUBT*CC; k += 256) {
            int c = k >> 7, p = k & (SUBT-1);
            float v = feat[c*NPIX + base + p];
            xt[p*PITCH + c] = v;
            xd[p*PD + c]    = dupf(v);
        }
        __syncthreads();
        if (tid < NL) gcnt[tid] += (unsigned int)cnt[tid];

        // S1
        {
            int c = tid & 63, kk = tid >> 6;
            #pragma unroll
            for (int l = 0; l < NL; l++) {
                int n = cnt[l];
                float a = 0.f;
                for (int k = kk; k < n; k += 4) a += xt[(int)lst[l][k]*PITCH + c];
                atomicAdd(&s1[l][c], a);
            }
        }
        // S2 rank-n updates: 4x4 tile per thread via FMA2
        #pragma unroll
        for (int l = 0; l < NL; l++) {
            int n = cnt[l];
            for (int k = 0; k < n; k++) {
                int j = (int)lst[l][k];
                ulonglong2 ap = *(const ulonglong2*)&xt[j*PITCH + rr*4];  // rows packed
                const u64* bp = &xd[j*PD + cr*4];                         // dup cols
                ulonglong2 b0 = *(const ulonglong2*)&bp[0];
                ulonglong2 b1 = *(const ulonglong2*)&bp[2];
                FMA2(acc[l][0], ap.x, b0.x); FMA2(acc[l][1], ap.x, b0.y);
                FMA2(acc[l][2], ap.x, b1.x); FMA2(acc[l][3], ap.x, b1.y);
                FMA2(acc[l][4], ap.y, b0.x); FMA2(acc[l][5], ap.y, b0.y);
                FMA2(acc[l][6], ap.y, b1.x); FMA2(acc[l][7], ap.y, b1.y);
            }
        }
    }
    __syncthreads();
    if (tid < NL) atomicAdd(&g_cnt[which][tid], gcnt[tid]);
    for (int k = tid; k < NL*CC; k += 256)
        atomicAdd(&g_S1[which][0][0] + k, (&s1[0][0])[k]);
    // write partials (no atomics)
    float* P = &g_part[which][blockIdx.x][0];
    #pragma unroll
    for (int l = 0; l < NL; l++) {
        int bb = l*CC*CC;
        #pragma unroll
        for (int s = 0; s < 4; s++) {
            float2 v0 = upk(acc[l][s]);       // rows rr*4+0, rr*4+1
            float2 v1 = upk(acc[l][4+s]);     // rows rr*4+2, rr*4+3
            int col = cr*4 + s;
            P[bb + (rr*4+0)*CC + col] = v0.x;
            P[bb + (rr*4+1)*CC + col] = v0.y;
            P[bb + (rr*4+2)*CC + col] = v1.x;
            P[bb + (rr*4+3)*CC + col] = v1.y;
        }
    }
}

// ================= reduce partials -> g_S2 =================
__global__ __launch_bounds__(256, 1) void reduce_kernel() {
    int e = blockIdx.x*256 + threadIdx.x;       // 0..65535
    int which = e >> 15, idx = e & 32767;
    float s = 0.f;
    #pragma unroll 2
    for (int b = 0; b < SBLK; b++) s += g_part[which][b][idx];
    (&g_S2[which][0][0])[idx] = s;
}

// ---------------- plain fp32 64x64x64 matmul (combine) ----------------
__device__ __forceinline__ void mm64_plain(float* __restrict__ C,
                                           const float* __restrict__ A,
                                           const float* __restrict__ B, int tid) {
    int rr = tid >> 4, cr = tid & 15;
    float acc[4][4] = {};
    #pragma unroll 4
    for (int k = 0; k < 64; k += 4) {
        float4 a[4], b[4];
        #pragma unroll
        for (int r = 0; r < 4; r++) a[r] = *(const float4*)&A[(rr*4 + r)*64 + k];
        #pragma unroll
        for (int i = 0; i < 4; i++) b[i] = *(const float4*)&B[(k + i)*64 + cr*4];
        #pragma unroll
        for (int r = 0; r < 4; r++) {
            float4 ar = a[r];
            acc[r][0] += ar.x*b[0].x + ar.y*b[1].x + ar.z*b[2].x + ar.w*b[3].x;
            acc[r][1] += ar.x*b[0].y + ar.y*b[1].y + ar.z*b[2].y + ar.w*b[3].y;
            acc[r][2] += ar.x*b[0].z + ar.y*b[1].z + ar.z*b[2].z + ar.w*b[3].z;
            acc[r][3] += ar.x*b[0].w + ar.y*b[1].w + ar.z*b[2].w + ar.w*b[3].w;
        }
    }
    #pragma unroll
    for (int r = 0; r < 4; r++)
        #pragma unroll
        for (int c = 0; c < 4; c++)
            C[(rr*4 + r)*64 + cr*4 + c] = acc[r][c];
}

// ---------------- packed 64x64x64 matmul: Cn/Cd = A@B (A dup fmt, B normal) ----------------
__device__ __forceinline__ void mm64_2(float* __restrict__ Cn, u64* __restrict__ Cd,
                                       const u64* __restrict__ Ad,
                                       const float* __restrict__ Bn,
                                       int tid, int nsform) {
    int rr = tid >> 4, cr = tid & 15;
    u64 acc[8];                       // [r*2 + c2], cols packed in pairs
    #pragma unroll
    for (int j = 0; j < 8; j++) acc[j] = 0ull;
    #pragma unroll 4
    for (int k = 0; k < 64; k += 2) {
        ulonglong2 a0 = *(const ulonglong2*)&Ad[(rr*4+0)*64 + k];
        ulonglong2 a1 = *(const ulonglong2*)&Ad[(rr*4+1)*64 + k];
        ulonglong2 a2 = *(const ulonglong2*)&Ad[(rr*4+2)*64 + k];
        ulonglong2 a3 = *(const ulonglong2*)&Ad[(rr*4+3)*64 + k];
        ulonglong2 b0 = *(const ulonglong2*)&Bn[(k+0)*64 + cr*4];
        ulonglong2 b1 = *(const ulonglong2*)&Bn[(k+1)*64 + cr*4];
        FMA2(acc[0], a0.x, b0.x); FMA2(acc[1], a0.x, b0.y);
        FMA2(acc[2], a1.x, b0.x); FMA2(acc[3], a1.x, b0.y);
        FMA2(acc[4], a2.x, b0.x); FMA2(acc[5], a2.x, b0.y);
        FMA2(acc[6], a3.x, b0.x); FMA2(acc[7], a3.x, b0.y);
        FMA2(acc[0], a0.y, b1.x); FMA2(acc[1], a0.y, b1.y);
        FMA2(acc[2], a1.y, b1.x); FMA2(acc[3], a1.y, b1.y);
        FMA2(acc[4], a2.y, b1.x); FMA2(acc[5], a2.y, b1.y);
        FMA2(acc[6], a3.y, b1.x); FMA2(acc[7], a3.y, b1.y);
    }
    #pragma unroll
    for (int r = 0; r < 4; r++) {
        int row = rr*4 + r, c0 = cr*4;
        float2 v0 = upk(acc[r*2+0]);
        float2 v1 = upk(acc[r*2+1]);
        if (nsform) {
            v0.x = ((row == c0+0) ? 1.5f : 0.f) - 0.5f*v0.x;
            v0.y = ((row == c0+1) ? 1.5f : 0.f) - 0.5f*v0.y;
            v1.x = ((row == c0+2) ? 1.5f : 0.f) - 0.5f*v1.x;
            v1.y = ((row == c0+3) ? 1.5f : 0.f) - 0.5f*v1.y;
        }
        *(u64*)&Cn[row*64 + c0]     = pk(v0.x, v0.y);
        *(u64*)&Cn[row*64 + c0 + 2] = pk(v1.x, v1.y);
        ulonglong2 d0; d0.x = dupf(v0.x); d0.y = dupf(v0.y);
        ulonglong2 d1; d1.x = dupf(v1.x); d1.y = dupf(v1.y);
        *(ulonglong2*)&Cd[row*64 + c0]     = d0;
        *(ulonglong2*)&Cd[row*64 + c0 + 2] = d1;
    }
}

// ============ Newton-Schulz: cov -> cov^{-1/2} (content) / cov^{1/2} (style) ============
__global__ __launch_bounds__(256, 1) void ns_kernel() {
    extern __shared__ char smraw[];
    float* Nb = (float*)smraw;                  // 4 x 4096 floats
    u64*   Db = (u64*)(smraw + 4*4096*4);       // 4 x 4096 dup-packed

    int lab = blockIdx.x >> 1, which = blockIdx.x & 1;
    int tid = threadIdx.x;
    __shared__ float mu[CC], rowsum[CC], s_sh;

    unsigned int n = g_cnt[which][lab];
    float fn = (float)n;
    if (tid < CC) mu[tid] = g_S1[which][lab][tid] / fmaxf(fn, 1.f);
    __syncthreads();
    float div = (fn - 1.f == 0.f) ? 1e-5f : (fn - 1.f);

    float* Y = Nb; u64* Yd = Db;                // buffer 0
    float* Z = Nb + 4096; u64* Zd = Db + 4096;  // buffer 1
    for (int k = tid; k < 4096; k += 256) {
        int i = k >> 6, j = k & 63;
        float a = (g_S2[which][lab][k] - fn*mu[i]*mu[j]) / div;
        if (which == 0 && i == j) a += 1.f;
        Y[k] = a;
    }
    __syncthreads();
    if (n <= 10u) {
        for (int k = tid; k < 4096; k += 256)
            g_WC[which][lab][k] = ((k >> 6) == (k & 63)) ? 1.f : 0.f;
        if (tid < CC) g_mu[which][lab][tid] = mu[tid];
        return;
    }
    if (tid < CC) {
        float sr = 0.f;
        for (int j = 0; j < 64; j++) sr += fabsf(Y[tid*64 + j]);
        rowsum[tid] = sr;
    }
    __syncthreads();
    if (tid == 0) {
        float m = 1e-10f;
        for (int i = 0; i < CC; i++) m = fmaxf(m, rowsum[i]);
        s_sh = m;
    }
    __syncthreads();
    float s = s_sh, inv_s = 1.f / s;
    for (int k = tid; k < 4096; k += 256) {
        float v = Y[k] * inv_s;
        Y[k] = v; Yd[k] = dupf(v);
        float id = ((k >> 6) == (k & 63)) ? 1.f : 0.f;
        Z[k] = id; Zd[k] = dupf(id);
    }
    __syncthreads();

    int iy = 0, iz = 1, iw = 2, iv = 3;
    for (int it = 0; it < NS_IT - 1; it++) {
        mm64_2(Nb+iw*4096, Db+iw*4096, Db+iz*4096, Nb+iy*4096, tid, 1); __syncthreads();
        mm64_2(Nb+iv*4096, Db+iv*4096, Db+iy*4096, Nb+iw*4096, tid, 0); __syncthreads();
        mm64_2(Nb+iy*4096, Db+iy*4096, Db+iw*4096, Nb+iz*4096, tid, 0); __syncthreads();
        int ny = iv, nz = iy, nv = iz;
        iy = ny; iz = nz; iv = nv;
    }
    // final iteration: only the needed branch
    mm64_2(Nb+iw*4096, Db+iw*4096, Db+iz*4096, Nb+iy*4096, tid, 1); __syncthreads();
    if (which == 1)
        mm64_2(Nb+iv*4096, Db+iv*4096, Db+iy*4096, Nb+iw*4096, tid, 0);   // Y_final
    else
        mm64_2(Nb+iv*4096, Db+iv*4096, Db+iw*4096, Nb+iz*4096, tid, 0);   // Z_final
    __syncthreads();

    float fac = (which == 0) ? rsqrtf(s) : sqrtf(s);
    const float* src = Nb + iv*4096;
    for (int k = tid; k < 4096; k += 256) g_WC[which][lab][k] = src[k] * fac;
    if (tid < CC) g_mu[which][lab][tid] = mu[tid];
}

// ============ combine: T = Co@Wh, beta = mu_s - T mu_c, valid ============
__global__ __launch_bounds__(256, 1) void combine_kernel() {
    extern __shared__ float csm[];
    float* Co = csm; float* Wh = csm + 4096; float* Tt = csm + 8192;
    int lab = blockIdx.x, tid = threadIdx.x;
    for (int k = tid; k < 4096; k += 256) {
        Co[k] = g_WC[1][lab][k];
        Wh[k] = g_WC[0][lab][k];
    }
    __syncthreads();
    mm64_plain(Tt, Co, Wh, tid);
    __syncthreads();
    for (int k = tid; k < 4096; k += 256) g_T[lab][k] = Tt[k];
    if (tid < CC) {
        float b = g_mu[1][lab][tid];
        const float* Tr = &Tt[tid*64];
        #pragma unroll 8
        for (int q = 0; q < CC; q++) b -= Tr[q] * g_mu[0][lab][q];
        g_beta[lab][tid] = b;
    }
    if (tid == 0) {
        float nc = (float)g_cnt[0][lab], ns = (float)g_cnt[1][lab];
        g_valid[lab] = (nc > 10.f) && (ns > 10.f) && (nc < 100.f*ns) && (ns < 100.f*nc);
    }
}

// ================= apply: out = valid ? T x + beta : x (f32x2) =================
__global__ __launch_bounds__(256, 1)
void apply_kernel(const float* __restrict__ cf, const int* __restrict__ cs,
                  float* __restrict__ out) {
    extern __shared__ float sm[];
    float* Ts  = sm;                    // [NL][TSTRIDE] bank-staggered
    float* bet = sm + NL*TSTRIDE;
    __shared__ int val[NL];
    int tid = threadIdx.x;
    for (int k = tid; k < NL*CC*CC; k += 256) {
        int l = k >> 12, o = k & 4095;
        Ts[l*TSTRIDE + o] = (&g_T[0][0])[k];
    }
    for (int k = tid; k < NL*CC; k += 256) bet[k] = (&g_beta[0][0])[k];
    if (tid < NL) val[tid] = g_valid[tid];
    __syncthreads();

    for (int t = blockIdx.x; t < NATILE; t += gridDim.x) {
        int p = t*APT + tid;
        int lab = cs[p] & 7;
        u64 xp[32];
        #pragma unroll
        for (int q2 = 0; q2 < 32; q2++) {
            float x0 = cf[(2*q2+0)*NPIX + p];
            float x1 = cf[(2*q2+1)*NPIX + p];
            xp[q2] = pk(x0, x1);
        }
        if (!val[lab]) {
            #pragma unroll
            for (int q2 = 0; q2 < 32; q2++) {
                float2 v = upk(xp[q2]);
                out[(2*q2+0)*NPIX + p] = v.x;
                out[(2*q2+1)*NPIX + p] = v.y;
            }
            continue;
        }
        const float* T  = Ts + lab*TSTRIDE;
        const float* bl = bet + lab*CC;
        #pragma unroll 2
        for (int c = 0; c < CC; c++) {
            u64 a0 = 0ull, a1 = 0ull;
            #pragma unroll
            for (int h = 0; h < 16; h++) {
                ulonglong2 tv = *(const ulonglong2*)&T[c*64 + h*4];
                FMA2(a0, tv.x, xp[2*h+0]);
                FMA2(a1, tv.y, xp[2*h+1]);
            }
            u64 ss; ADD2(ss, a0, a1);
            float2 f = upk(ss);
            out[c*NPIX + p] = f.x + f.y + bl[c];
        }
    }
}

extern "C" void kernel_launch(void* const* d_in, const int* in_sizes, int n_in,
                              void* d_out, int out_size) {
    const float* cf = (const float*)d_in[0];
    const float* sf = (const float*)d_in[1];
    const int*   cs = (const int*)d_in[2];
    const int*   ss = (const int*)d_in[3];
    float* out = (float*)d_out;

    int stats_smem = SUBT*PITCH*4 + SUBT*PD*8;          // 102400
    int ns_smem    = 4*4096*4 + 4*4096*8;               // 196608
    int comb_smem  = 3*4096*4;                          // 49152
    int apply_smem = NL*TSTRIDE*4 + NL*CC*4;            // 133248

    cudaFuncSetAttribute(stats_kernel,  cudaFuncAttributeMaxDynamicSharedMemorySize, stats_smem);
    cudaFuncSetAttribute(ns_kernel,     cudaFuncAttributeMaxDynamicSharedMemorySize, ns_smem);
    cudaFuncSetAttribute(combine_kernel,cudaFuncAttributeMaxDynamicSharedMemorySize, comb_smem);
    cudaFuncSetAttribute(apply_kernel,  cudaFuncAttributeMaxDynamicSharedMemorySize, apply_smem);

    zero_kernel<<<1, 256>>>();
    stats_kernel<<<dim3(SBLK, 2), 256, stats_smem>>>(cf, sf, cs, ss);
    reduce_kernel<<<256, 256>>>();
    ns_kernel<<<16, 256, ns_smem>>>();
    combine_kernel<<<NL, 256, comb_smem>>>();
    apply_kernel<<<148, 256, apply_smem>>>(cf, cs, out);
}

// round 5
// speedup vs baseline: 1.4779x; 1.4779x over previous
#include <cuda_runtime.h>

#define CC 64
#define NPIX (512*512)
#define NL 8
#define NBLK 256
#define PXB 1024
#define CH 512
#define MAXV 520
#define PITCH 68
#define TSTRIDE 4100
#define NS_IT 5
#define APT 256
#define NATILE (NPIX/APT)

// ---------------- global scratch (statics only; no runtime allocations) ----------------
__device__ int   g_bcnt[2][NBLK][NL];
__device__ int   g_boff[2][NBLK][NL];
__device__ int   g_lbase[2][NL];
__device__ int   g_cnt[2][NL];
__device__ float g_sorted[2][NPIX*CC];          // label-sorted features, [pos][64] row-major
__device__ float g_p2[2][MAXV][CC*CC];          // per-chunk S2 partials
__device__ float g_p1[2][MAXV][CC];             // per-chunk S1 partials
__device__ float g_S1[2][NL][CC];
__device__ float g_S2[2][NL][CC*CC];
__device__ float g_WC[2][NL][CC*CC];            // [0]=cov_c^{-1/2}, [1]=cov_s^{1/2}
__device__ float g_mu[2][NL][CC];
__device__ float g_T[NL][CC*CC];
__device__ float g_beta[NL][CC];
__device__ int   g_valid[NL];

// ================= 1. hist: per-block per-label counts =================
__global__ __launch_bounds__(256, 1)
void hist_kernel(const int* __restrict__ cs, const int* __restrict__ ss) {
    __shared__ int hc[NL];
    int dir = blockIdx.y;
    const int* seg = dir ? ss : cs;
    int b = blockIdx.x, tid = threadIdx.x;
    if (tid < NL) hc[tid] = 0;
    __syncthreads();
    #pragma unroll
    for (int wv = 0; wv < 4; wv++)
        atomicAdd(&hc[seg[b*PXB + wv*256 + tid] & 7], 1);
    __syncthreads();
    if (tid < NL) g_bcnt[dir][b][tid] = hc[tid];
}

// ================= 2. scan: block offsets + label bases + totals =================
__global__ __launch_bounds__(256, 1) void scan_kernel() {
    __shared__ int sc[256];
    __shared__ int tot[16];
    int tid = threadIdx.x;
    for (int pair = 0; pair < 16; pair++) {
        int dir = pair >> 3, l = pair & 7;
        int v = g_bcnt[dir][tid][l];
        sc[tid] = v;
        __syncthreads();
        for (int off = 1; off < 256; off <<= 1) {
            int t = (tid >= off) ? sc[tid - off] : 0;
            __syncthreads();
            sc[tid] += t;
            __syncthreads();
        }
        g_boff[dir][tid][l] = sc[tid] - v;          // exclusive prefix over blocks
        if (tid == 255) tot[pair] = sc[255];
        __syncthreads();
    }
    if (tid < 16) {
        int dir = tid >> 3, l = tid & 7;
        int base = 0;
        for (int ll = 0; ll < l; ll++) base += tot[dir*8 + ll];
        g_lbase[dir][l] = base;
        g_cnt[dir][l]   = tot[tid];
    }
}

// ================= 3. scatter: stable counting-sort of feature rows =================
__global__ __launch_bounds__(256, 1)
void scatter_kernel(const float* __restrict__ cf, const float* __restrict__ sf,
                    const int* __restrict__ cs, const int* __restrict__ ss) {
    extern __shared__ float xs[];           // [256][65]
    __shared__ int pos[256];
    __shared__ int wcnt[8][8];              // [warp][label]
    __shared__ int woff[NL];
    __shared__ int bo[NL];
    int dir = blockIdx.y;
    const float* feat = dir ? sf : cf;
    const int*   seg  = dir ? ss : cs;
    int b = blockIdx.x, tid = threadIdx.x;
    int lane = tid & 31, w = tid >> 5;
    float* dst = &g_sorted[dir][0];
    if (tid < NL) { bo[tid] = g_lbase[dir][tid] + g_boff[dir][b][tid]; woff[tid] = 0; }
    __syncthreads();

    for (int wv = 0; wv < 4; wv++) {
        int p = b*PXB + wv*256 + tid;
        int lab = seg[p] & 7;
        if (tid < 64) wcnt[tid >> 3][tid & 7] = 0;
        __syncthreads();
        unsigned m = __match_any_sync(0xffffffffu, lab);
        int rnk = __popc(m & ((1u << lane) - 1u));
        if (rnk == 0) wcnt[w][lab] = __popc(m);
        __syncthreads();
        int before = woff[lab];
        #pragma unroll
        for (int w2 = 0; w2 < 8; w2++) if (w2 < w) before += wcnt[w2][lab];
        pos[tid] = bo[lab] + before + rnk;
        // stage this wave's features (coalesced reads, padded smem)
        #pragma unroll 8
        for (int c = 0; c < CC; c++)
            xs[tid*65 + c] = feat[c*NPIX + p];
        __syncthreads();
        if (tid < NL) {
            int t = 0;
            #pragma unroll
            for (int w2 = 0; w2 < 8; w2++) t += wcnt[w2][tid];
            woff[tid] += t;
        }
        // write rows out: 256B-contiguous per pixel, 4 px per 256-thread sweep
        for (int k = tid; k < 256*CC; k += 256) {
            int px = k >> 6, c = k & 63;
            dst[pos[px]*CC + c] = xs[px*65 + c];
        }
        __syncthreads();
    }
}

// ================= 4. stats: dense per-chunk SYRK on sorted rows =================
__global__ __launch_bounds__(256, 2) void stats_kernel() {
    __shared__ float xs[128*PITCH];
    __shared__ int cb[NL+1], kb[NL];
    __shared__ int sl, sks, ske;
    __shared__ float s1p[4][CC];
    int dir = blockIdx.y, v = blockIdx.x, tid = threadIdx.x;
    if (tid == 0) {
        int c = 0, k = 0;
        for (int l = 0; l < NL; l++) {
            int n = g_cnt[dir][l];
            kb[l] = k; cb[l] = c;
            c += (n + CH - 1) / CH; k += n;
        }
        cb[NL] = c;
        if (v < c) {
            int l = 0;
            while (cb[l+1] <= v) l++;
            int ks = kb[l] + (v - cb[l]) * CH;
            int ke = kb[l] + g_cnt[dir][l];
            if (ke > ks + CH) ke = ks + CH;
            sl = l; sks = ks; ske = ke;
        } else sl = -1;
    }
    __syncthreads();
    if (sl < 0) return;
    int ks = sks, ke = ske;
    int rr = tid >> 4, cr = tid & 15;
    int c1 = tid & 63, g1 = tid >> 6;
    float acc[16] = {};
    float s1r = 0.f;
    const float* src = &g_sorted[dir][0];

    for (int kt = ks; kt < ke; kt += 128) {
        int rows = ke - kt; if (rows > 128) rows = 128;
        __syncthreads();
        for (int k = tid; k < rows*CC; k += 256) {
            int r = k >> 6, cc2 = k & 63;
            xs[r*PITCH + cc2] = src[(kt + r)*CC + cc2];
        }
        __syncthreads();
        #pragma unroll 4
        for (int j = 0; j < rows; j++) {
            float4 a  = *(const float4*)&xs[j*PITCH + rr*4];
            float4 bv = *(const float4*)&xs[j*PITCH + cr*4];
            acc[0]  += a.x*bv.x; acc[1]  += a.x*bv.y; acc[2]  += a.x*bv.z; acc[3]  += a.x*bv.w;
            acc[4]  += a.y*bv.x; acc[5]  += a.y*bv.y; acc[6]  += a.y*bv.z; acc[7]  += a.y*bv.w;
            acc[8]  += a.z*bv.x; acc[9]  += a.z*bv.y; acc[10] += a.z*bv.z; acc[11] += a.z*bv.w;
            acc[12] += a.w*bv.x; acc[13] += a.w*bv.y; acc[14] += a.w*bv.z; acc[15] += a.w*bv.w;
        }
        for (int j = g1; j < rows; j += 4) s1r += xs[j*PITCH + c1];
    }
    float* P = &g_p2[dir][v][0];
    #pragma unroll
    for (int r = 0; r < 4; r++)
        *(float4*)&P[(rr*4 + r)*CC + cr*4] =
            make_float4(acc[r*4+0], acc[r*4+1], acc[r*4+2], acc[r*4+3]);
    s1p[g1][c1] = s1r;
    __syncthreads();
    if (tid < CC)
        g_p1[dir][v][tid] = s1p[0][tid] + s1p[1][tid] + s1p[2][tid] + s1p[3][tid];
}

// ================= 5. reduce: per-label sums of chunk partials =================
__global__ __launch_bounds__(256, 1) void reduce_kernel() {
    __shared__ int rs, re;
    int dir = blockIdx.x >> 3, l = blockIdx.x & 7, tid = threadIdx.x;
    if (tid == 0) {
        int c = 0, cs0 = 0, n0 = 0;
        for (int ll = 0; ll < NL; ll++) {
            int n = g_cnt[dir][ll];
            int nc = (n + CH - 1) / CH;
            if (ll == l) { cs0 = c; n0 = nc; }
            c += nc;
        }
        rs = cs0; re = cs0 + n0;
    }
    __syncthreads();
    int a = rs, b = re;
    for (int e = tid; e < CC*CC; e += 256) {
        float s = 0.f;
        for (int v = a; v < b; v++) s += g_p2[dir][v][e];
        g_S2[dir][l][e] = s;
    }
    if (tid < CC) {
        float s = 0.f;
        for (int v = a; v < b; v++) s += g_p1[dir][v][tid];
        g_S1[dir][l][tid] = s;
    }
}

// ---------------- 64x64x64 in-block matmul, 256 threads ----------------
__device__ __forceinline__ void mm64(float* __restrict__ C,
                                     const float* __restrict__ A,
                                     const float* __restrict__ B,
                                     int tid, int nsform) {
    int rr = tid >> 4, cr = tid & 15;
    float acc[4][4] = {};
    #pragma unroll 4
    for (int k = 0; k < 64; k += 4) {
        float4 a[4], b[4];
        #pragma unroll
        for (int r = 0; r < 4; r++) a[r] = *(const float4*)&A[(rr*4 + r)*64 + k];
        #pragma unroll
        for (int i = 0; i < 4; i++) b[i] = *(const float4*)&B[(k + i)*64 + cr*4];
        #pragma unroll
        for (int r = 0; r < 4; r++) {
            float4 ar = a[r];
            acc[r][0] += ar.x*b[0].x + ar.y*b[1].x + ar.z*b[2].x + ar.w*b[3].x;
            acc[r][1] += ar.x*b[0].y + ar.y*b[1].y + ar.z*b[2].y + ar.w*b[3].y;
            acc[r][2] += ar.x*b[0].z + ar.y*b[1].z + ar.z*b[2].z + ar.w*b[3].z;
            acc[r][3] += ar.x*b[0].w + ar.y*b[1].w + ar.z*b[2].w + ar.w*b[3].w;
        }
    }
    #pragma unroll
    for (int r = 0; r < 4; r++)
        #pragma unroll
        for (int c = 0; c < 4; c++) {
            float v = acc[r][c];
            if (nsform) v = ((rr*4 + r) == (cr*4 + c) ? 1.5f : 0.f) - 0.5f*v;
            C[(rr*4 + r)*64 + cr*4 + c] = v;
        }
}

// ============ 6. Newton-Schulz: cov -> cov^{-1/2} (content) / cov^{1/2} (style) ============
__global__ __launch_bounds__(256, 1) void ns_kernel() {
    extern __shared__ float sm[];
    float *Yp = sm, *Zp = sm + 4096, *Wp = sm + 8192, *Vp = sm + 12288;
    int lab = blockIdx.x >> 1, which = blockIdx.x & 1;
    int tid = threadIdx.x;
    __shared__ float mu[CC], rowsum[CC], s_sh;

    int n = g_cnt[which][lab];
    float fn = (float)n;
    if (tid < CC) mu[tid] = g_S1[which][lab][tid] / fmaxf(fn, 1.f);
    __syncthreads();
    float div = (fn - 1.f == 0.f) ? 1e-5f : (fn - 1.f);
    for (int k = tid; k < 4096; k += 256) {
        int i = k >> 6, j = k & 63;
        float a = (g_S2[which][lab][k] - fn*mu[i]*mu[j]) / div;
        if (which == 0 && i == j) a += 1.f;
        Yp[k] = a;
    }
    __syncthreads();
    if (n <= 10) {   // invalid label -> result never used; emit identity
        for (int k = tid; k < 4096; k += 256)
            g_WC[which][lab][k] = ((k >> 6) == (k & 63)) ? 1.f : 0.f;
        if (tid < CC) g_mu[which][lab][tid] = mu[tid];
        return;
    }
    if (tid < CC) {
        float sr = 0.f;
        for (int j = 0; j < 64; j++) sr += fabsf(Yp[tid*64 + j]);
        rowsum[tid] = sr;
    }
    __syncthreads();
    if (tid == 0) {
        float m = 1e-10f;
        for (int i = 0; i < CC; i++) m = fmaxf(m, rowsum[i]);
        s_sh = m;
    }
    __syncthreads();
    float s = s_sh, inv_s = 1.f / s;
    for (int k = tid; k < 4096; k += 256) {
        Yp[k] *= inv_s;
        Zp[k] = ((k >> 6) == (k & 63)) ? 1.f : 0.f;
    }
    __syncthreads();
    for (int it = 0; it < NS_IT; it++) {
        mm64(Wp, Zp, Yp, tid, 1);   // W = 1.5I - 0.5 Z@Y
        __syncthreads();
        mm64(Vp, Yp, Wp, tid, 0);   // newY = Y@W
        __syncthreads();
        mm64(Yp, Wp, Zp, tid, 0);   // newZ = W@Z (into old Y buffer)
        __syncthreads();
        float* t = Yp; Yp = Vp; Vp = Zp; Zp = t;
    }
    float fac = (which == 0) ? rsqrtf(s) : sqrtf(s);
    const float* srcm = (which == 0) ? Zp : Yp;
    for (int k = tid; k < 4096; k += 256) g_WC[which][lab][k] = srcm[k] * fac;
    if (tid < CC) g_mu[which][lab][tid] = mu[tid];
}

// ============ 7. combine: T = Co@Wh, beta = mu_s - T mu_c, valid ============
__global__ __launch_bounds__(256, 1) void combine_kernel() {
    extern __shared__ float csm[];
    float* Co = csm; float* Wh = csm + 4096; float* Tt = csm + 8192;
    int lab = blockIdx.x, tid = threadIdx.x;
    for (int k = tid; k < 4096; k += 256) {
        Co[k] = g_WC[1][lab][k];
        Wh[k] = g_WC[0][lab][k];
    }
    __syncthreads();
    mm64(Tt, Co, Wh, tid, 0);
    __syncthreads();
    for (int k = tid; k < 4096; k += 256) g_T[lab][k] = Tt[k];
    if (tid < CC) {
        float b = g_mu[1][lab][tid];
        const float* Tr = &Tt[tid*64];
        #pragma unroll 8
        for (int q = 0; q < CC; q++) b -= Tr[q] * g_mu[0][lab][q];
        g_beta[lab][tid] = b;
    }
    if (tid == 0) {
        float nc = (float)g_cnt[0][lab], ns = (float)g_cnt[1][lab];
        g_valid[lab] = (nc > 10.f) && (ns > 10.f) && (nc < 100.f*ns) && (ns < 100.f*nc);
    }
}

// ================= 8. apply: out = valid ? T x + beta : x =================
__global__ __launch_bounds__(256, 1)
void apply_kernel(const float* __restrict__ cf, const int* __restrict__ cs,
                  float* __restrict__ out) {
    extern __shared__ float sm[];
    float* Ts  = sm;                     // [NL][TSTRIDE] bank-staggered
    float* bet = sm + NL*TSTRIDE;
    __shared__ int val[NL];
    int tid = threadIdx.x;
    for (int k = tid; k < NL*CC*CC; k += 256) {
        int l = k >> 12, o = k & 4095;
        Ts[l*TSTRIDE + o] = (&g_T[0][0])[k];
    }
    for (int k = tid; k < NL*CC; k += 256) bet[k] = (&g_beta[0][0])[k];
    if (tid < NL) val[tid] = g_valid[tid];
    __syncthreads();

    for (int t = blockIdx.x; t < NATILE; t += gridDim.x) {
        int p = t*APT + tid;
        int lab = cs[p] & 7;
        float x[CC];
        #pragma unroll
        for (int c = 0; c < CC; c++) x[c] = cf[c*NPIX + p];
        if (!val[lab]) {
            #pragma unroll
            for (int c = 0; c < CC; c++) out[c*NPIX + p] = x[c];
            continue;
        }
        const float* T  = Ts + lab*TSTRIDE;
        const float* bl = bet + lab*CC;
        for (int c0 = 0; c0 < CC; c0 += 4) {
            float a0 = 0.f, a1 = 0.f, a2 = 0.f, a3 = 0.f;
            #pragma unroll
            for (int q = 0; q < CC; q += 4) {
                float4 t0 = *(const float4*)&T[(c0+0)*64 + q];
                float4 t1 = *(const float4*)&T[(c0+1)*64 + q];
                float4 t2 = *(const float4*)&T[(c0+2)*64 + q];
                float4 t3 = *(const float4*)&T[(c0+3)*64 + q];
                a0 += t0.x*x[q] + t0.y*x[q+1] + t0.z*x[q+2] + t0.w*x[q+3];
                a1 += t1.x*x[q] + t1.y*x[q+1] + t1.z*x[q+2] + t1.w*x[q+3];
                a2 += t2.x*x[q] + t2.y*x[q+1] + t2.z*x[q+2] + t2.w*x[q+3];
                a3 += t3.x*x[q] + t3.y*x[q+1] + t3.z*x[q+2] + t3.w*x[q+3];
            }
            out[(c0+0)*NPIX + p] = a0 + bl[c0+0];
            out[(c0+1)*NPIX + p] = a1 + bl[c0+1];
            out[(c0+2)*NPIX + p] = a2 + bl[c0+2];
            out[(c0+3)*NPIX + p] = a3 + bl[c0+3];
        }
    }
}

extern "C" void kernel_launch(void* const* d_in, const int* in_sizes, int n_in,
                              void* d_out, int out_size) {
    const float* cf = (const float*)d_in[0];
    const float* sf = (const float*)d_in[1];
    const int*   cs = (const int*)d_in[2];
    const int*   ss = (const int*)d_in[3];
    float* out = (float*)d_out;

    int scat_smem  = 256*65*4;                   // 66560
    int ns_smem    = 4*4096*4;                   // 65536
    int comb_smem  = 3*4096*4;                   // 49152
    int apply_smem = NL*TSTRIDE*4 + NL*CC*4;     // 133248

    cudaFuncSetAttribute(scatter_kernel, cudaFuncAttributeMaxDynamicSharedMemorySize, scat_smem);
    cudaFuncSetAttribute(ns_kernel,      cudaFuncAttributeMaxDynamicSharedMemorySize, ns_smem);
    cudaFuncSetAttribute(combine_kernel, cudaFuncAttributeMaxDynamicSharedMemorySize, comb_smem);
    cudaFuncSetAttribute(apply_kernel,   cudaFuncAttributeMaxDynamicSharedMemorySize, apply_smem);

    hist_kernel<<<dim3(NBLK, 2), 256>>>(cs, ss);                 // launch 1
    scan_kernel<<<1, 256>>>();                                   // launch 2
    scatter_kernel<<<dim3(NBLK, 2), 256, scat_smem>>>(cf, sf, cs, ss); // launch 3
    stats_kernel<<<dim3(MAXV, 2), 256>>>();                      // launch 4 (profiled slot)
    reduce_kernel<<<16, 256>>>();                                // launch 5
    ns_kernel<<<16, 256, ns_smem>>>();                           // launch 6
    combine_kernel<<<NL, 256, comb_smem>>>();                    // launch 7
    apply_kernel<<<148, 256, apply_smem>>>(cf, cs, out);         // launch 8
}

// round 6
// speedup vs baseline: 1.4837x; 1.0039x over previous
#include <cuda_runtime.h>

#define CC 64
#define NPIX (512*512)
#define NL 8
#define NBLK 256
#define PXB 1024
#define CH 512
#define MAXV 520
#define PITCH 68
#define NS_IT 5

// ---------------- global scratch (statics only; no runtime allocations) ----------------
__device__ int   g_bcnt[2][NBLK][NL];
__device__ int   g_boff[2][NBLK][NL];
__device__ int   g_lbase[2][NL];
__device__ int   g_cnt[2][NL];
__device__ float g_sorted[2][NPIX*CC];          // label-sorted features, [pos][64] row-major
__device__ int   g_posmap[NPIX];                // content: orig pixel -> sorted pos
__device__ float g_ysort[NPIX*CC];              // transformed sorted rows
__device__ float g_p2[2][MAXV][4][CC*CC];       // per-chunk, per-kgroup S2 partials
__device__ float g_p1[2][MAXV][4][CC];
__device__ float g_S1[2][NL][CC];
__device__ float g_S2[2][NL][CC*CC];
__device__ float g_WC[2][NL][CC*CC];            // [0]=cov_c^{-1/2}, [1]=cov_s^{1/2}
__device__ float g_mu[2][NL][CC];
__device__ float g_T[NL][CC*CC];
__device__ float g_beta[NL][CC];
__device__ int   g_valid[NL];

// ================= 1. hist =================
__global__ __launch_bounds__(256, 1)
void hist_kernel(const int* __restrict__ cs, const int* __restrict__ ss) {
    __shared__ int hc[NL];
    int dir = blockIdx.y;
    const int* seg = dir ? ss : cs;
    int b = blockIdx.x, tid = threadIdx.x;
    if (tid < NL) hc[tid] = 0;
    __syncthreads();
    #pragma unroll
    for (int wv = 0; wv < 4; wv++)
        atomicAdd(&hc[seg[b*PXB + wv*256 + tid] & 7], 1);
    __syncthreads();
    if (tid < NL) g_bcnt[dir][b][tid] = hc[tid];
}

// ================= 2. scan =================
__global__ __launch_bounds__(256, 1) void scan_kernel() {
    __shared__ int sc[256];
    __shared__ int tot[16];
    int tid = threadIdx.x;
    for (int pair = 0; pair < 16; pair++) {
        int dir = pair >> 3, l = pair & 7;
        int v = g_bcnt[dir][tid][l];
        sc[tid] = v;
        __syncthreads();
        for (int off = 1; off < 256; off <<= 1) {
            int t = (tid >= off) ? sc[tid - off] : 0;
            __syncthreads();
            sc[tid] += t;
            __syncthreads();
        }
        g_boff[dir][tid][l] = sc[tid] - v;
        if (tid == 255) tot[pair] = sc[255];
        __syncthreads();
    }
    if (tid < 16) {
        int dir = tid >> 3, l = tid & 7;
        int base = 0;
        for (int ll = 0; ll < l; ll++) base += tot[dir*8 + ll];
        g_lbase[dir][l] = base;
        g_cnt[dir][l]   = tot[tid];
    }
}

// ================= 3. scatter: stable counting sort + inverse perm =================
__global__ __launch_bounds__(256, 1)
void scatter_kernel(const float* __restrict__ cf, const float* __restrict__ sf,
                    const int* __restrict__ cs, const int* __restrict__ ss) {
    extern __shared__ float xs[];           // [256][65]
    __shared__ int pos[256];
    __shared__ int wcnt[8][8];
    __shared__ int woff[NL];
    __shared__ int bo[NL];
    int dir = blockIdx.y;
    const float* feat = dir ? sf : cf;
    const int*   seg  = dir ? ss : cs;
    int b = blockIdx.x, tid = threadIdx.x;
    int lane = tid & 31, w = tid >> 5;
    float* dst = &g_sorted[dir][0];
    if (tid < NL) { bo[tid] = g_lbase[dir][tid] + g_boff[dir][b][tid]; woff[tid] = 0; }
    __syncthreads();

    for (int wv = 0; wv < 4; wv++) {
        int p = b*PXB + wv*256 + tid;
        int lab = seg[p] & 7;
        if (tid < 64) wcnt[tid >> 3][tid & 7] = 0;
        __syncthreads();
        unsigned m = __match_any_sync(0xffffffffu, lab);
        int rnk = __popc(m & ((1u << lane) - 1u));
        if (rnk == 0) wcnt[w][lab] = __popc(m);
        __syncthreads();
        int before = woff[lab];
        #pragma unroll
        for (int w2 = 0; w2 < 8; w2++) if (w2 < w) before += wcnt[w2][lab];
        int mypos = bo[lab] + before + rnk;
        pos[tid] = mypos;
        if (dir == 0) g_posmap[p] = mypos;
        #pragma unroll 8
        for (int c = 0; c < CC; c++)
            xs[tid*65 + c] = feat[c*NPIX + p];
        __syncthreads();
        if (tid < NL) {
            int t = 0;
            #pragma unroll
            for (int w2 = 0; w2 < 8; w2++) t += wcnt[w2][tid];
            woff[tid] += t;
        }
        for (int k = tid; k < 256*CC; k += 256) {
            int px = k >> 6, c = k & 63;
            dst[pos[px]*CC + c] = xs[px*65 + c];
        }
        __syncthreads();
    }
}

// ================= 4. stats: 8x8-tiled SYRK with 4-way k-split =================
__global__ __launch_bounds__(256, 2) void stats_kernel() {
    __shared__ float xs[128*PITCH];
    __shared__ int cb[NL+1], kb[NL];
    __shared__ int sl, sks, ske;
    int dir = blockIdx.y, v = blockIdx.x, tid = threadIdx.x;
    if (tid == 0) {
        int c = 0, k = 0;
        for (int l = 0; l < NL; l++) {
            int n = g_cnt[dir][l];
            kb[l] = k; cb[l] = c;
            c += (n + CH - 1) / CH; k += n;
        }
        cb[NL] = c;
        if (v < c) {
            int l = 0;
            while (cb[l+1] <= v) l++;
            int ks = kb[l] + (v - cb[l]) * CH;
            int ke = kb[l] + g_cnt[dir][l];
            if (ke > ks + CH) ke = ks + CH;
            sl = l; sks = ks; ske = ke;
        } else sl = -1;
    }
    __syncthreads();
    if (sl < 0) return;
    int ks = sks, ke = ske;
    int g = tid >> 6, t64 = tid & 63;
    int rr = t64 >> 3, cr = t64 & 7;
    float acc[8][8] = {};
    float s1r = 0.f;
    const float* src = &g_sorted[dir][0];

    for (int kt = ks; kt < ke; kt += 128) {
        int rows = ke - kt; if (rows > 128) rows = 128;
        __syncthreads();
        for (int k = tid; k < rows*CC; k += 256) {
            int r = k >> 6, cc2 = k & 63;
            xs[r*PITCH + cc2] = src[(kt + r)*CC + cc2];
        }
        __syncthreads();
        #pragma unroll 2
        for (int j = g; j < rows; j += 4) {
            const float* row = &xs[j*PITCH];
            float4 a0 = *(const float4*)&row[rr*8];
            float4 a1 = *(const float4*)&row[rr*8 + 4];
            float4 b0 = *(const float4*)&row[cr*8];
            float4 b1 = *(const float4*)&row[cr*8 + 4];
            float av[8] = {a0.x,a0.y,a0.z,a0.w,a1.x,a1.y,a1.z,a1.w};
            float bv[8] = {b0.x,b0.y,b0.z,b0.w,b1.x,b1.y,b1.z,b1.w};
            #pragma unroll
            for (int r = 0; r < 8; r++)
                #pragma unroll
                for (int s = 0; s < 8; s++)
                    acc[r][s] += av[r]*bv[s];
            s1r += row[t64];
        }
    }
    float* P = &g_p2[dir][v][g][0];
    #pragma unroll
    for (int r = 0; r < 8; r++) {
        *(float4*)&P[(rr*8 + r)*CC + cr*8]     =
            make_float4(acc[r][0], acc[r][1], acc[r][2], acc[r][3]);
        *(float4*)&P[(rr*8 + r)*CC + cr*8 + 4] =
            make_float4(acc[r][4], acc[r][5], acc[r][6], acc[r][7]);
    }
    g_p1[dir][v][g][t64] = s1r;
}

// ================= 5. reduce =================
__global__ __launch_bounds__(256, 1) void reduce_kernel() {
    __shared__ int rs, re;
    int dir = blockIdx.x >> 3, l = blockIdx.x & 7, tid = threadIdx.x;
    int slice = blockIdx.y;                  // 4 slices of 1024 elems
    if (tid == 0) {
        int c = 0, cs0 = 0, n0 = 0;
        for (int ll = 0; ll < NL; ll++) {
            int n = g_cnt[dir][ll];
            int nc = (n + CH - 1) / CH;
            if (ll == l) { cs0 = c; n0 = nc; }
            c += nc;
        }
        rs = cs0; re = cs0 + n0;
    }
    __syncthreads();
    int a = rs, b = re;
    for (int e = slice*1024 + tid; e < slice*1024 + 1024; e += 256) {
        float s = 0.f;
        for (int v = a; v < b; v++)
            s += g_p2[dir][v][0][e] + g_p2[dir][v][1][e]
               + g_p2[dir][v][2][e] + g_p2[dir][v][3][e];
        g_S2[dir][l][e] = s;
    }
    if (slice == 0 && tid < CC) {
        float s = 0.f;
        for (int v = a; v < b; v++)
            s += g_p1[dir][v][0][tid] + g_p1[dir][v][1][tid]
               + g_p1[dir][v][2][tid] + g_p1[dir][v][3][tid];
        g_S1[dir][l][tid] = s;
    }
}

// ---------------- 64x64x64 in-block matmul, 256 threads ----------------
__device__ __forceinline__ void mm64(float* __restrict__ C,
                                     const float* __restrict__ A,
                                     const float* __restrict__ B,
                                     int tid, int nsform) {
    int rr = tid >> 4, cr = tid & 15;
    float acc[4][4] = {};
    #pragma unroll 4
    for (int k = 0; k < 64; k += 4) {
        float4 a[4], b[4];
        #pragma unroll
        for (int r = 0; r < 4; r++) a[r] = *(const float4*)&A[(rr*4 + r)*64 + k];
        #pragma unroll
        for (int i = 0; i < 4; i++) b[i] = *(const float4*)&B[(k + i)*64 + cr*4];
        #pragma unroll
        for (int r = 0; r < 4; r++) {
            float4 ar = a[r];
            acc[r][0] += ar.x*b[0].x + ar.y*b[1].x + ar.z*b[2].x + ar.w*b[3].x;
            acc[r][1] += ar.x*b[0].y + ar.y*b[1].y + ar.z*b[2].y + ar.w*b[3].y;
            acc[r][2] += ar.x*b[0].z + ar.y*b[1].z + ar.z*b[2].z + ar.w*b[3].z;
            acc[r][3] += ar.x*b[0].w + ar.y*b[1].w + ar.z*b[2].w + ar.w*b[3].w;
        }
    }
    #pragma unroll
    for (int r = 0; r < 4; r++)
        #pragma unroll
        for (int c = 0; c < 4; c++) {
            float v = acc[r][c];
            if (nsform) v = ((rr*4 + r) == (cr*4 + c) ? 1.5f : 0.f) - 0.5f*v;
            C[(rr*4 + r)*64 + cr*4 + c] = v;
        }
}

// ============ 6. Newton-Schulz ============
__global__ __launch_bounds__(256, 1) void ns_kernel() {
    extern __shared__ float sm[];
    float *Yp = sm, *Zp = sm + 4096, *Wp = sm + 8192, *Vp = sm + 12288;
    int lab = blockIdx.x >> 1, which = blockIdx.x & 1;
    int tid = threadIdx.x;
    __shared__ float mu[CC], rowsum[CC], s_sh;

    int n = g_cnt[which][lab];
    float fn = (float)n;
    if (tid < CC) mu[tid] = g_S1[which][lab][tid] / fmaxf(fn, 1.f);
    __syncthreads();
    float div = (fn - 1.f == 0.f) ? 1e-5f : (fn - 1.f);
    for (int k = tid; k < 4096; k += 256) {
        int i = k >> 6, j = k & 63;
        float a = (g_S2[which][lab][k] - fn*mu[i]*mu[j]) / div;
        if (which == 0 && i == j) a += 1.f;
        Yp[k] = a;
    }
    __syncthreads();
    if (n <= 10) {
        for (int k = tid; k < 4096; k += 256)
            g_WC[which][lab][k] = ((k >> 6) == (k & 63)) ? 1.f : 0.f;
        if (tid < CC) g_mu[which][lab][tid] = mu[tid];
        return;
    }
    if (tid < CC) {
        float sr = 0.f;
        for (int j = 0; j < 64; j++) sr += fabsf(Yp[tid*64 + j]);
        rowsum[tid] = sr;
    }
    __syncthreads();
    if (tid == 0) {
        float m = 1e-10f;
        for (int i = 0; i < CC; i++) m = fmaxf(m, rowsum[i]);
        s_sh = m;
    }
    __syncthreads();
    float s = s_sh, inv_s = 1.f / s;
    for (int k = tid; k < 4096; k += 256) {
        Yp[k] *= inv_s;
        Zp[k] = ((k >> 6) == (k & 63)) ? 1.f : 0.f;
    }
    __syncthreads();
    for (int it = 0; it < NS_IT; it++) {
        mm64(Wp, Zp, Yp, tid, 1);
        __syncthreads();
        mm64(Vp, Yp, Wp, tid, 0);
        __syncthreads();
        mm64(Yp, Wp, Zp, tid, 0);
        __syncthreads();
        float* t = Yp; Yp = Vp; Vp = Zp; Zp = t;
    }
    float fac = (which == 0) ? rsqrtf(s) : sqrtf(s);
    const float* srcm = (which == 0) ? Zp : Yp;
    for (int k = tid; k < 4096; k += 256) g_WC[which][lab][k] = srcm[k] * fac;
    if (tid < CC) g_mu[which][lab][tid] = mu[tid];
}

// ============ 7. combine ============
__global__ __launch_bounds__(256, 1) void combine_kernel() {
    extern __shared__ float csm[];
    float* Co = csm; float* Wh = csm + 4096; float* Tt = csm + 8192;
    int lab = blockIdx.x, tid = threadIdx.x;
    for (int k = tid; k < 4096; k += 256) {
        Co[k] = g_WC[1][lab][k];
        Wh[k] = g_WC[0][lab][k];
    }
    __syncthreads();
    mm64(Tt, Co, Wh, tid, 0);
    __syncthreads();
    for (int k = tid; k < 4096; k += 256) g_T[lab][k] = Tt[k];
    if (tid < CC) {
        float b = g_mu[1][lab][tid];
        const float* Tr = &Tt[tid*64];
        #pragma unroll 8
        for (int q = 0; q < CC; q++) b -= Tr[q] * g_mu[0][lab][q];
        g_beta[lab][tid] = b;
    }
    if (tid == 0) {
        float nc = (float)g_cnt[0][lab], ns = (float)g_cnt[1][lab];
        g_valid[lab] = (nc > 10.f) && (ns > 10.f) && (nc < 100.f*ns) && (ns < 100.f*nc);
    }
}

// ============ 8. apply on sorted rows: ysort = T x + beta (or x if invalid) ============
__global__ __launch_bounds__(256, 2) void apply_kernel() {
    extern __shared__ float asmem[];
    float* T0 = asmem;            // 4096
    float* T1 = asmem + 4096;     // 4096
    __shared__ int lb[NL];
    __shared__ float bet[2][CC];
    __shared__ int labA, labB, vA, vB;
    int tid = threadIdx.x;
    int pos0 = blockIdx.x * 256;
    if (tid < NL) lb[tid] = g_lbase[0][tid];
    __syncthreads();
    if (tid == 0) {
        int la = 0, lz = 0;
        #pragma unroll
        for (int ll = 1; ll < NL; ll++) {
            if (pos0       >= lb[ll]) la = ll;
            if (pos0 + 255 >= lb[ll]) lz = ll;
        }
        labA = la; labB = lz;
        vA = g_valid[la]; vB = g_valid[lz];
    }
    __syncthreads();
    int la = labA, lz = labB;
    for (int k = tid; k < 4096; k += 256) T0[k] = g_T[la][k];
    if (lz != la)
        for (int k = tid; k < 4096; k += 256) T1[k] = g_T[lz][k];
    if (tid < CC) {
        bet[0][tid] = g_beta[la][tid];
        bet[1][tid] = g_beta[lz][tid];
    }
    __syncthreads();

    int pos = pos0 + tid;
    int l = 0;
    #pragma unroll
    for (int ll = 1; ll < NL; ll++) if (pos >= lb[ll]) l = ll;

    const float* xr = &g_sorted[0][(long)pos*CC];
    float x[CC];
    #pragma unroll
    for (int i = 0; i < 16; i++) {
        float4 v = *(const float4*)&xr[i*4];
        x[i*4] = v.x; x[i*4+1] = v.y; x[i*4+2] = v.z; x[i*4+3] = v.w;
    }
    float* yr = &g_ysort[(long)pos*CC];
    int sel = (l == la) ? 0 : 1;
    int valid = sel ? vB : vA;
    if (!valid) {
        #pragma unroll
        for (int i = 0; i < 16; i++)
            *(float4*)&yr[i*4] = *(const float4*)&xr[i*4];
        return;
    }
    const float* T  = sel ? T1 : T0;
    const float* bl = bet[sel];
    for (int c0 = 0; c0 < CC; c0 += 4) {
        float a0 = bl[c0], a1 = bl[c0+1], a2 = bl[c0+2], a3 = bl[c0+3];
        #pragma unroll
        for (int q = 0; q < CC; q += 4) {
            float4 t0 = *(const float4*)&T[(c0+0)*64 + q];
            float4 t1 = *(const float4*)&T[(c0+1)*64 + q];
            float4 t2 = *(const float4*)&T[(c0+2)*64 + q];
            float4 t3 = *(const float4*)&T[(c0+3)*64 + q];
            a0 += t0.x*x[q] + t0.y*x[q+1] + t0.z*x[q+2] + t0.w*x[q+3];
            a1 += t1.x*x[q] + t1.y*x[q+1] + t1.z*x[q+2] + t1.w*x[q+3];
            a2 += t2.x*x[q] + t2.y*x[q+1] + t2.z*x[q+2] + t2.w*x[q+3];
            a3 += t3.x*x[q] + t3.y*x[q+1] + t3.z*x[q+2] + t3.w*x[q+3];
        }
        *(float4*)&yr[c0] = make_float4(a0, a1, a2, a3);
    }
}

// ============ 9. writeout: gather sorted rows back to channel-major ============
__global__ __launch_bounds__(256, 2) void writeout_kernel(float* __restrict__ out) {
    int p = blockIdx.x*256 + threadIdx.x;
    int pos = g_posmap[p];
    const float* yr = &g_ysort[(long)pos*CC];
    float y[CC];
    #pragma unroll
    for (int i = 0; i < 16; i++) {
        float4 v = *(const float4*)&yr[i*4];
        y[i*4] = v.x; y[i*4+1] = v.y; y[i*4+2] = v.z; y[i*4+3] = v.w;
    }
    #pragma unroll
    for (int c = 0; c < CC; c++) out[c*NPIX + p] = y[c];
}

extern "C" void kernel_launch(void* const* d_in, const int* in_sizes, int n_in,
                              void* d_out, int out_size) {
    const float* cf = (const float*)d_in[0];
    const float* sf = (const float*)d_in[1];
    const int*   cs = (const int*)d_in[2];
    const int*   ss = (const int*)d_in[3];
    float* out = (float*)d_out;

    int scat_smem  = 256*65*4;      // 66560
    int ns_smem    = 4*4096*4;      // 65536
    int comb_smem  = 3*4096*4;      // 49152
    int apply_smem = 2*4096*4;      // 32768

    cudaFuncSetAttribute(scatter_kernel, cudaFuncAttributeMaxDynamicSharedMemorySize, scat_smem);
    cudaFuncSetAttribute(ns_kernel,      cudaFuncAttributeMaxDynamicSharedMemorySize, ns_smem);
    cudaFuncSetAttribute(combine_kernel, cudaFuncAttributeMaxDynamicSharedMemorySize, comb_smem);
    cudaFuncSetAttribute(apply_kernel,   cudaFuncAttributeMaxDynamicSharedMemorySize, apply_smem);

    hist_kernel<<<dim3(NBLK, 2), 256>>>(cs, ss);                        // 1
    scan_kernel<<<1, 256>>>();                                          // 2
    scatter_kernel<<<dim3(NBLK, 2), 256, scat_smem>>>(cf, sf, cs, ss);  // 3
    stats_kernel<<<dim3(MAXV, 2), 256>>>();                             // 4 (profiled)
    reduce_kernel<<<dim3(16, 4), 256>>>();                              // 5
    ns_kernel<<<16, 256, ns_smem>>>();                                  // 6
    combine_kernel<<<NL, 256, comb_smem>>>();                           // 7
    apply_kernel<<<NPIX/256, 256, apply_smem>>>();                      // 8
    writeout_kernel<<<NPIX/256, 256>>>(out);                            // 9
}

// round 7
// speedup vs baseline: 1.9144x; 1.2903x over previous
#include <cuda_runtime.h>

#define CC 64
#define NPIX (512*512)
#define NL 8
#define NBLK 256
#define PXB 1024
#define CH 512
#define MAXV 520
#define SPITCH 72
#define NS_IT 5

// ---------------- global scratch (statics only; no runtime allocations) ----------------
__device__ int   g_bcnt[2][NBLK][NL];
__device__ int   g_boff[2][NBLK][NL];
__device__ int   g_lbase[2][NL];
__device__ int   g_cnt[2][NL];
__device__ float g_sorted[2][NPIX*CC];          // label-sorted features, [pos][64] row-major
__device__ int   g_posmap[NPIX];                // content: orig pixel -> sorted pos
__device__ float g_ysort[NPIX*CC];              // transformed sorted rows
__device__ float g_p2[2][MAXV][CC*CC];          // per-chunk S2 partials
__device__ float g_p1[2][MAXV][CC];
__device__ float g_S1[2][NL][CC];
__device__ float g_S2[2][NL][CC*CC];
__device__ float g_WC[2][NL][CC*CC];            // [0]=cov_c^{-1/2}, [1]=cov_s^{1/2}
__device__ float g_mu[2][NL][CC];
__device__ float g_T[NL][CC*CC];
__device__ float g_beta[NL][CC];
__device__ int   g_valid[NL];

// ---------------- tf32 mma helpers ----------------
__device__ __forceinline__ unsigned f2tf(float f) {
    unsigned r;
    asm("cvt.rna.tf32.f32 %0, %1;" : "=r"(r) : "f"(f));
    return r;
}
__device__ __forceinline__ void mma_tf32(float4& d,
                                         unsigned a0, unsigned a1, unsigned a2, unsigned a3,
                                         unsigned b0, unsigned b1) {
    asm volatile(
        "mma.sync.aligned.m16n8k8.row.col.f32.tf32.tf32.f32 "
        "{%0,%1,%2,%3}, {%4,%5,%6,%7}, {%8,%9}, {%0,%1,%2,%3};"
        : "+f"(d.x), "+f"(d.y), "+f"(d.z), "+f"(d.w)
        : "r"(a0), "r"(a1), "r"(a2), "r"(a3), "r"(b0), "r"(b1));
}

// ================= 1. hist =================
__global__ __launch_bounds__(256, 1)
void hist_kernel(const int* __restrict__ cs, const int* __restrict__ ss) {
    __shared__ int hc[NL];
    int dir = blockIdx.y;
    const int* seg = dir ? ss : cs;
    int b = blockIdx.x, tid = threadIdx.x;
    if (tid < NL) hc[tid] = 0;
    __syncthreads();
    #pragma unroll
    for (int wv = 0; wv < 4; wv++)
        atomicAdd(&hc[seg[b*PXB + wv*256 + tid] & 7], 1);
    __syncthreads();
    if (tid < NL) g_bcnt[dir][b][tid] = hc[tid];
}

// ================= 2. scan =================
__global__ __launch_bounds__(256, 1) void scan_kernel() {
    __shared__ int sc[256];
    __shared__ int tot[16];
    int tid = threadIdx.x;
    for (int pair = 0; pair < 16; pair++) {
        int dir = pair >> 3, l = pair & 7;
        int v = g_bcnt[dir][tid][l];
        sc[tid] = v;
        __syncthreads();
        for (int off = 1; off < 256; off <<= 1) {
            int t = (tid >= off) ? sc[tid - off] : 0;
            __syncthreads();
            sc[tid] += t;
            __syncthreads();
        }
        g_boff[dir][tid][l] = sc[tid] - v;
        if (tid == 255) tot[pair] = sc[255];
        __syncthreads();
    }
    if (tid < 16) {
        int dir = tid >> 3, l = tid & 7;
        int base = 0;
        for (int ll = 0; ll < l; ll++) base += tot[dir*8 + ll];
        g_lbase[dir][l] = base;
        g_cnt[dir][l]   = tot[tid];
    }
}

// ================= 3. scatter: stable counting sort + inverse perm =================
__global__ __launch_bounds__(256, 1)
void scatter_kernel(const float* __restrict__ cf, const float* __restrict__ sf,
                    const int* __restrict__ cs, const int* __restrict__ ss) {
    extern __shared__ float xs[];           // [256][65]
    __shared__ int pos[256];
    __shared__ int wcnt[8][8];
    __shared__ int woff[NL];
    __shared__ int bo[NL];
    int dir = blockIdx.y;
    const float* feat = dir ? sf : cf;
    const int*   seg  = dir ? ss : cs;
    int b = blockIdx.x, tid = threadIdx.x;
    int lane = tid & 31, w = tid >> 5;
    float* dst = &g_sorted[dir][0];
    if (tid < NL) { bo[tid] = g_lbase[dir][tid] + g_boff[dir][b][tid]; woff[tid] = 0; }
    __syncthreads();

    for (int wv = 0; wv < 4; wv++) {
        int p = b*PXB + wv*256 + tid;
        int lab = seg[p] & 7;
        if (tid < 64) wcnt[tid >> 3][tid & 7] = 0;
        __syncthreads();
        unsigned m = __match_any_sync(0xffffffffu, lab);
        int rnk = __popc(m & ((1u << lane) - 1u));
        if (rnk == 0) wcnt[w][lab] = __popc(m);
        __syncthreads();
        int before = woff[lab];
        #pragma unroll
        for (int w2 = 0; w2 < 8; w2++) if (w2 < w) before += wcnt[w2][lab];
        int mypos = bo[lab] + before + rnk;
        pos[tid] = mypos;
        if (dir == 0) g_posmap[p] = mypos;
        #pragma unroll 8
        for (int c = 0; c < CC; c++)
            xs[tid*65 + c] = feat[c*NPIX + p];
        __syncthreads();
        if (tid < NL) {
            int t = 0;
            #pragma unroll
            for (int w2 = 0; w2 < 8; w2++) t += wcnt[w2][tid];
            woff[tid] += t;
        }
        for (int k = tid; k < 256*CC; k += 256) {
            int px = k >> 6, c = k & 63;
            dst[pos[px]*CC + c] = xs[px*65 + c];
        }
        __syncthreads();
    }
}

// ================= 4. stats: tf32 tensor-core SYRK per chunk =================
__global__ __launch_bounds__(256, 2) void stats_kernel() {
    __shared__ unsigned xs[128*SPITCH];
    __shared__ int cb[NL+1], kb[NL];
    __shared__ int sl, sks, ske;
    __shared__ float s1p[4][CC];
    int dir = blockIdx.y, v = blockIdx.x, tid = threadIdx.x;
    if (tid == 0) {
        int c = 0, k = 0;
        for (int l = 0; l < NL; l++) {
            int n = g_cnt[dir][l];
            kb[l] = k; cb[l] = c;
            c += (n + CH - 1) / CH; k += n;
        }
        cb[NL] = c;
        if (v < c) {
            int l = 0;
            while (cb[l+1] <= v) l++;
            int ks = kb[l] + (v - cb[l]) * CH;
            int ke = kb[l] + g_cnt[dir][l];
            if (ke > ks + CH) ke = ks + CH;
            sl = l; sks = ks; ske = ke;
        } else sl = -1;
    }
    __syncthreads();
    if (sl < 0) return;
    int ks = sks, ke = ske;

    int w = tid >> 5, lane = tid & 31;
    int g = lane >> 2, t = lane & 3;
    int rowbase = (w & 3) * 16, colbase = (w >> 2) * 32;
    int t64 = tid & 63, g1 = tid >> 6;

    float4 dacc[4];
    #pragma unroll
    for (int j = 0; j < 4; j++) dacc[j] = make_float4(0.f, 0.f, 0.f, 0.f);
    float s1r = 0.f;
    const float* src = &g_sorted[dir][0];

    for (int kt = ks; kt < ke; kt += 128) {
        __syncthreads();
        // stage + tf32-round, zero-pad past label end
        for (int k = tid; k < 128*CC; k += 256) {
            int r = k >> 6, c = k & 63;
            float f = (kt + r < ke) ? src[(kt + r)*CC + c] : 0.f;
            xs[r*SPITCH + c] = f2tf(f);
        }
        __syncthreads();
        // S1 ride-along (zeros contribute nothing)
        #pragma unroll 4
        for (int j = g1; j < 128; j += 4) s1r += __uint_as_float(xs[j*SPITCH + t64]);
        // tensor SYRK: 16 k-steps of 8 pixels
        #pragma unroll
        for (int kk = 0; kk < 128; kk += 8) {
            unsigned a0 = xs[(kk + t    )*SPITCH + rowbase + g];
            unsigned a1 = xs[(kk + t    )*SPITCH + rowbase + g + 8];
            unsigned a2 = xs[(kk + t + 4)*SPITCH + rowbase + g];
            unsigned a3 = xs[(kk + t + 4)*SPITCH + rowbase + g + 8];
            #pragma unroll
            for (int j = 0; j < 4; j++) {
                unsigned b0 = xs[(kk + t    )*SPITCH + colbase + j*8 + g];
                unsigned b1 = xs[(kk + t + 4)*SPITCH + colbase + j*8 + g];
                mma_tf32(dacc[j], a0, a1, a2, a3, b0, b1);
            }
        }
    }
    // write C partials: warp owns 16x32 slab, thread holds (g,2t) pairs
    float* P = &g_p2[dir][v][0];
    #pragma unroll
    for (int j = 0; j < 4; j++) {
        int col = colbase + j*8 + 2*t;
        *(float2*)&P[(rowbase + g    )*CC + col] = make_float2(dacc[j].x, dacc[j].y);
        *(float2*)&P[(rowbase + g + 8)*CC + col] = make_float2(dacc[j].z, dacc[j].w);
    }
    s1p[g1][t64] = s1r;
    __syncthreads();
    if (tid < CC)
        g_p1[dir][v][tid] = s1p[0][tid] + s1p[1][tid] + s1p[2][tid] + s1p[3][tid];
}

// ================= 5. reduce =================
__global__ __launch_bounds__(256, 1) void reduce_kernel() {
    __shared__ int rs, re;
    int dir = blockIdx.x >> 3, l = blockIdx.x & 7, tid = threadIdx.x;
    int slice = blockIdx.y;                  // 4 slices of 1024 elems
    if (tid == 0) {
        int c = 0, cs0 = 0, n0 = 0;
        for (int ll = 0; ll < NL; ll++) {
            int n = g_cnt[dir][ll];
            int nc = (n + CH - 1) / CH;
            if (ll == l) { cs0 = c; n0 = nc; }
            c += nc;
        }
        rs = cs0; re = cs0 + n0;
    }
    __syncthreads();
    int a = rs, b = re;
    for (int e = slice*1024 + tid; e < slice*1024 + 1024; e += 256) {
        float s = 0.f;
        for (int v = a; v < b; v++) s += g_p2[dir][v][e];
        g_S2[dir][l][e] = s;
    }
    if (slice == 0 && tid < CC) {
        float s = 0.f;
        for (int v = a; v < b; v++) s += g_p1[dir][v][tid];
        g_S1[dir][l][tid] = s;
    }
}

// ---------------- 64x64x64 in-block matmul, 256 threads ----------------
__device__ __forceinline__ void mm64(float* __restrict__ C,
                                     const float* __restrict__ A,
                                     const float* __restrict__ B,
                                     int tid, int nsform) {
    int rr = tid >> 4, cr = tid & 15;
    float acc[4][4] = {};
    #pragma unroll 4
    for (int k = 0; k < 64; k += 4) {
        float4 a[4], b[4];
        #pragma unroll
        for (int r = 0; r < 4; r++) a[r] = *(const float4*)&A[(rr*4 + r)*64 + k];
        #pragma unroll
        for (int i = 0; i < 4; i++) b[i] = *(const float4*)&B[(k + i)*64 + cr*4];
        #pragma unroll
        for (int r = 0; r < 4; r++) {
            float4 ar = a[r];
            acc[r][0] += ar.x*b[0].x + ar.y*b[1].x + ar.z*b[2].x + ar.w*b[3].x;
            acc[r][1] += ar.x*b[0].y + ar.y*b[1].y + ar.z*b[2].y + ar.w*b[3].y;
            acc[r][2] += ar.x*b[0].z + ar.y*b[1].z + ar.z*b[2].z + ar.w*b[3].z;
            acc[r][3] += ar.x*b[0].w + ar.y*b[1].w + ar.z*b[2].w + ar.w*b[3].w;
        }
    }
    #pragma unroll
    for (int r = 0; r < 4; r++)
        #pragma unroll
        for (int c = 0; c < 4; c++) {
            float v = acc[r][c];
            if (nsform) v = ((rr*4 + r) == (cr*4 + c) ? 1.5f : 0.f) - 0.5f*v;
            C[(rr*4 + r)*64 + cr*4 + c] = v;
        }
}

// ============ 6. Newton-Schulz ============
__global__ __launch_bounds__(256, 1) void ns_kernel() {
    extern __shared__ float sm[];
    float *Yp = sm, *Zp = sm + 4096, *Wp = sm + 8192, *Vp = sm + 12288;
    int lab = blockIdx.x >> 1, which = blockIdx.x & 1;
    int tid = threadIdx.x;
    __shared__ float mu[CC], rowsum[CC], s_sh;

    int n = g_cnt[which][lab];
    float fn = (float)n;
    if (tid < CC) mu[tid] = g_S1[which][lab][tid] / fmaxf(fn, 1.f);
    __syncthreads();
    float div = (fn - 1.f == 0.f) ? 1e-5f : (fn - 1.f);
    for (int k = tid; k < 4096; k += 256) {
        int i = k >> 6, j = k & 63;
        float a = (g_S2[which][lab][k] - fn*mu[i]*mu[j]) / div;
        if (which == 0 && i == j) a += 1.f;
        Yp[k] = a;
    }
    __syncthreads();
    if (n <= 10) {
        for (int k = tid; k < 4096; k += 256)
            g_WC[which][lab][k] = ((k >> 6) == (k & 63)) ? 1.f : 0.f;
        if (tid < CC) g_mu[which][lab][tid] = mu[tid];
        return;
    }
    if (tid < CC) {
        float sr = 0.f;
        for (int j = 0; j < 64; j++) sr += fabsf(Yp[tid*64 + j]);
        rowsum[tid] = sr;
    }
    __syncthreads();
    if (tid == 0) {
        float m = 1e-10f;
        for (int i = 0; i < CC; i++) m = fmaxf(m, rowsum[i]);
        s_sh = m;
    }
    __syncthreads();
    float s = s_sh, inv_s = 1.f / s;
    for (int k = tid; k < 4096; k += 256) {
        Yp[k] *= inv_s;
        Zp[k] = ((k >> 6) == (k & 63)) ? 1.f : 0.f;
    }
    __syncthreads();
    for (int it = 0; it < NS_IT; it++) {
        mm64(Wp, Zp, Yp, tid, 1);
        __syncthreads();
        mm64(Vp, Yp, Wp, tid, 0);
        __syncthreads();
        mm64(Yp, Wp, Zp, tid, 0);
        __syncthreads();
        float* t = Yp; Yp = Vp; Vp = Zp; Zp = t;
    }
    float fac = (which == 0) ? rsqrtf(s) : sqrtf(s);
    const float* srcm = (which == 0) ? Zp : Yp;
    for (int k = tid; k < 4096; k += 256) g_WC[which][lab][k] = srcm[k] * fac;
    if (tid < CC) g_mu[which][lab][tid] = mu[tid];
}

// ============ 7. combine ============
__global__ __launch_bounds__(256, 1) void combine_kernel() {
    extern __shared__ float csm[];
    float* Co = csm; float* Wh = csm + 4096; float* Tt = csm + 8192;
    int lab = blockIdx.x, tid = threadIdx.x;
    for (int k = tid; k < 4096; k += 256) {
        Co[k] = g_WC[1][lab][k];
        Wh[k] = g_WC[0][lab][k];
    }
    __syncthreads();
    mm64(Tt, Co, Wh, tid, 0);
    __syncthreads();
    for (int k = tid; k < 4096; k += 256) g_T[lab][k] = Tt[k];
    if (tid < CC) {
        float b = g_mu[1][lab][tid];
        const float* Tr = &Tt[tid*64];
        #pragma unroll 8
        for (int q = 0; q < CC; q++) b -= Tr[q] * g_mu[0][lab][q];
        g_beta[lab][tid] = b;
    }
    if (tid == 0) {
        float nc = (float)g_cnt[0][lab], ns = (float)g_cnt[1][lab];
        g_valid[lab] = (nc > 10.f) && (ns > 10.f) && (nc < 100.f*ns) && (ns < 100.f*nc);
    }
}

// ============ 8. apply on sorted rows: ysort = T x + beta (or x if invalid) ============
__global__ __launch_bounds__(256, 2) void apply_kernel() {
    extern __shared__ float asmem[];
    float* T0 = asmem;            // 4096
    float* T1 = asmem + 4096;     // 4096
    __shared__ int lb[NL];
    __shared__ float bet[2][CC];
    __shared__ int labA, labB, vA, vB;
    int tid = threadIdx.x;
    int pos0 = blockIdx.x * 256;
    if (tid < NL) lb[tid] = g_lbase[0][tid];
    __syncthreads();
    if (tid == 0) {
        int la = 0, lz = 0;
        #pragma unroll
        for (int ll = 1; ll < NL; ll++) {
            if (pos0       >= lb[ll]) la = ll;
            if (pos0 + 255 >= lb[ll]) lz = ll;
        }
        labA = la; labB = lz;
        vA = g_valid[la]; vB = g_valid[lz];
    }
    __syncthreads();
    int la = labA, lz = labB;
    for (int k = tid; k < 4096; k += 256) T0[k] = g_T[la][k];
    if (lz != la)
        for (int k = tid; k < 4096; k += 256) T1[k] = g_T[lz][k];
    if (tid < CC) {
        bet[0][tid] = g_beta[la][tid];
        bet[1][tid] = g_beta[lz][tid];
    }
    __syncthreads();

    int pos = pos0 + tid;
    int l = 0;
    #pragma unroll
    for (int ll = 1; ll < NL; ll++) if (pos >= lb[ll]) l = ll;

    const float* xr = &g_sorted[0][(long)pos*CC];
    float x[CC];
    #pragma unroll
    for (int i = 0; i < 16; i++) {
        float4 v = *(const float4*)&xr[i*4];
        x[i*4] = v.x; x[i*4+1] = v.y; x[i*4+2] = v.z; x[i*4+3] = v.w;
    }
    float* yr = &g_ysort[(long)pos*CC];
    int sel = (l == la) ? 0 : 1;
    int valid = sel ? vB : vA;
    if (!valid) {
        #pragma unroll
        for (int i = 0; i < 16; i++)
            *(float4*)&yr[i*4] = *(const float4*)&xr[i*4];
        return;
    }
    const float* T  = sel ? T1 : T0;
    const float* bl = bet[sel];
    for (int c0 = 0; c0 < CC; c0 += 4) {
        float a0 = bl[c0], a1 = bl[c0+1], a2 = bl[c0+2], a3 = bl[c0+3];
        #pragma unroll
        for (int q = 0; q < CC; q += 4) {
            float4 t0 = *(const float4*)&T[(c0+0)*64 + q];
            float4 t1 = *(const float4*)&T[(c0+1)*64 + q];
            float4 t2 = *(const float4*)&T[(c0+2)*64 + q];
            float4 t3 = *(const float4*)&T[(c0+3)*64 + q];
            a0 += t0.x*x[q] + t0.y*x[q+1] + t0.z*x[q+2] + t0.w*x[q+3];
            a1 += t1.x*x[q] + t1.y*x[q+1] + t1.z*x[q+2] + t1.w*x[q+3];
            a2 += t2.x*x[q] + t2.y*x[q+1] + t2.z*x[q+2] + t2.w*x[q+3];
            a3 += t3.x*x[q] + t3.y*x[q+1] + t3.z*x[q+2] + t3.w*x[q+3];
        }
        *(float4*)&yr[c0] = make_float4(a0, a1, a2, a3);
    }
}

// ============ 9. writeout: gather sorted rows back to channel-major ============
__global__ __launch_bounds__(256, 2) void writeout_kernel(float* __restrict__ out) {
    int p = blockIdx.x*256 + threadIdx.x;
    int pos = g_posmap[p];
    const float* yr = &g_ysort[(long)pos*CC];
    float y[CC];
    #pragma unroll
    for (int i = 0; i < 16; i++) {
        float4 v = *(const float4*)&yr[i*4];
        y[i*4] = v.x; y[i*4+1] = v.y; y[i*4+2] = v.z; y[i*4+3] = v.w;
    }
    #pragma unroll
    for (int c = 0; c < CC; c++) out[c*NPIX + p] = y[c];
}

extern "C" void kernel_launch(void* const* d_in, const int* in_sizes, int n_in,
                              void* d_out, int out_size) {
    const float* cf = (const float*)d_in[0];
    const float* sf = (const float*)d_in[1];
    const int*   cs = (const int*)d_in[2];
    const int*   ss = (const int*)d_in[3];
    float* out = (float*)d_out;

    int scat_smem  = 256*65*4;      // 66560
    int ns_smem    = 4*4096*4;      // 65536
    int comb_smem  = 3*4096*4;      // 49152
    int apply_smem = 2*4096*4;      // 32768

    cudaFuncSetAttribute(scatter_kernel, cudaFuncAttributeMaxDynamicSharedMemorySize, scat_smem);
    cudaFuncSetAttribute(ns_kernel,      cudaFuncAttributeMaxDynamicSharedMemorySize, ns_smem);
    cudaFuncSetAttribute(combine_kernel, cudaFuncAttributeMaxDynamicSharedMemorySize, comb_smem);
    cudaFuncSetAttribute(apply_kernel,   cudaFuncAttributeMaxDynamicSharedMemorySize, apply_smem);

    hist_kernel<<<dim3(NBLK, 2), 256>>>(cs, ss);                        // 1
    scan_kernel<<<1, 256>>>();                                          // 2
    scatter_kernel<<<dim3(NBLK, 2), 256, scat_smem>>>(cf, sf, cs, ss);  // 3
    stats_kernel<<<dim3(MAXV, 2), 256>>>();                             // 4 (profiled)
    reduce_kernel<<<dim3(16, 4), 256>>>();                              // 5
    ns_kernel<<<16, 256, ns_smem>>>();                                  // 6
    combine_kernel<<<NL, 256, comb_smem>>>();                           // 7
    apply_kernel<<<NPIX/256, 256, apply_smem>>>();                      // 8
    writeout_kernel<<<NPIX/256, 256>>>(out);                            // 9
}

// round 8
// speedup vs baseline: 1.9256x; 1.0059x over previous
#include <cuda_runtime.h>

#define CC 64
#define NPIX (512*512)
#define NL 8
#define NBLK 256
#define PXB 1024
#define CH 512
#define MAXV 520
#define SPITCH 72
#define NS_IT 5

// ---------------- global scratch (statics only; no runtime allocations) ----------------
__device__ int   g_bcnt[2][NBLK][NL];
__device__ int   g_boff[2][NBLK][NL];
__device__ int   g_lbase[2][NL];
__device__ int   g_cnt[2][NL];
__device__ float g_sorted[2][NPIX*CC];          // label-sorted features, [pos][64] row-major
__device__ int   g_posmap[NPIX];                // content: orig pixel -> sorted pos
__device__ float g_ysort[NPIX*CC];              // transformed sorted rows
__device__ float g_p2[2][MAXV][CC*CC];          // per-chunk S2 partials
__device__ float g_p1[2][MAXV][CC];
__device__ float g_S1[2][NL][CC];
__device__ float g_S2[2][NL][CC*CC];
__device__ float g_WC[2][NL][CC*CC];            // [0]=cov_c^{-1/2}, [1]=cov_s^{1/2}
__device__ float g_mu[2][NL][CC];
__device__ float g_T[NL][CC*CC];
__device__ float g_beta[NL][CC];
__device__ int   g_valid[NL];

// ---------------- tf32 mma helpers ----------------
__device__ __forceinline__ unsigned f2tf(float f) {
    unsigned r;
    asm("cvt.rna.tf32.f32 %0, %1;" : "=r"(r) : "f"(f));
    return r;
}
__device__ __forceinline__ void mma_tf32(float4& d,
                                         unsigned a0, unsigned a1, unsigned a2, unsigned a3,
                                         unsigned b0, unsigned b1) {
    asm volatile(
        "mma.sync.aligned.m16n8k8.row.col.f32.tf32.tf32.f32 "
        "{%0,%1,%2,%3}, {%4,%5,%6,%7}, {%8,%9}, {%0,%1,%2,%3};"
        : "+f"(d.x), "+f"(d.y), "+f"(d.z), "+f"(d.w)
        : "r"(a0), "r"(a1), "r"(a2), "r"(a3), "r"(b0), "r"(b1));
}

// ================= 1. hist =================
__global__ __launch_bounds__(256, 1)
void hist_kernel(const int* __restrict__ cs, const int* __restrict__ ss) {
    __shared__ int hc[NL];
    int dir = blockIdx.y;
    const int* seg = dir ? ss : cs;
    int b = blockIdx.x, tid = threadIdx.x;
    if (tid < NL) hc[tid] = 0;
    __syncthreads();
    #pragma unroll
    for (int wv = 0; wv < 4; wv++)
        atomicAdd(&hc[seg[b*PXB + wv*256 + tid] & 7], 1);
    __syncthreads();
    if (tid < NL) g_bcnt[dir][b][tid] = hc[tid];
}

// ================= 2. scan =================
__global__ __launch_bounds__(256, 1) void scan_kernel() {
    __shared__ int sc[256];
    __shared__ int tot[16];
    int tid = threadIdx.x;
    for (int pair = 0; pair < 16; pair++) {
        int dir = pair >> 3, l = pair & 7;
        int v = g_bcnt[dir][tid][l];
        sc[tid] = v;
        __syncthreads();
        for (int off = 1; off < 256; off <<= 1) {
            int t = (tid >= off) ? sc[tid - off] : 0;
            __syncthreads();
            sc[tid] += t;
            __syncthreads();
        }
        g_boff[dir][tid][l] = sc[tid] - v;
        if (tid == 255) tot[pair] = sc[255];
        __syncthreads();
    }
    if (tid < 16) {
        int dir = tid >> 3, l = tid & 7;
        int base = 0;
        for (int ll = 0; ll < l; ll++) base += tot[dir*8 + ll];
        g_lbase[dir][l] = base;
        g_cnt[dir][l]   = tot[tid];
    }
}

// ================= 3. scatter: stable counting sort + inverse perm =================
__global__ __launch_bounds__(256, 1)
void scatter_kernel(const float* __restrict__ cf, const float* __restrict__ sf,
                    const int* __restrict__ cs, const int* __restrict__ ss) {
    extern __shared__ float xs[];           // [256][65]
    __shared__ int pos[256];
    __shared__ int wcnt[8][8];
    __shared__ int woff[NL];
    __shared__ int bo[NL];
    int dir = blockIdx.y;
    const float* feat = dir ? sf : cf;
    const int*   seg  = dir ? ss : cs;
    int b = blockIdx.x, tid = threadIdx.x;
    int lane = tid & 31, w = tid >> 5;
    float* dst = &g_sorted[dir][0];
    if (tid < NL) { bo[tid] = g_lbase[dir][tid] + g_boff[dir][b][tid]; woff[tid] = 0; }
    __syncthreads();

    for (int wv = 0; wv < 4; wv++) {
        int p = b*PXB + wv*256 + tid;
        int lab = seg[p] & 7;
        if (tid < 64) wcnt[tid >> 3][tid & 7] = 0;
        __syncthreads();
        unsigned m = __match_any_sync(0xffffffffu, lab);
        int rnk = __popc(m & ((1u << lane) - 1u));
        if (rnk == 0) wcnt[w][lab] = __popc(m);
        __syncthreads();
        int before = woff[lab];
        #pragma unroll
        for (int w2 = 0; w2 < 8; w2++) if (w2 < w) before += wcnt[w2][lab];
        int mypos = bo[lab] + before + rnk;
        pos[tid] = mypos;
        if (dir == 0) g_posmap[p] = mypos;
        #pragma unroll 8
        for (int c = 0; c < CC; c++)
            xs[tid*65 + c] = feat[c*NPIX + p];
        __syncthreads();
        if (tid < NL) {
            int t = 0;
            #pragma unroll
            for (int w2 = 0; w2 < 8; w2++) t += wcnt[w2][tid];
            woff[tid] += t;
        }
        for (int k = tid; k < 256*CC; k += 256) {
            int px = k >> 6, c = k & 63;
            dst[pos[px]*CC + c] = xs[px*65 + c];
        }
        __syncthreads();
    }
}

// ================= 4. stats: tf32 tensor-core SYRK per chunk =================
__global__ __launch_bounds__(256, 2) void stats_kernel() {
    __shared__ unsigned xs[128*SPITCH];
    __shared__ int cb[NL+1], kb[NL];
    __shared__ int sl, sks, ske;
    __shared__ float s1p[4][CC];
    int dir = blockIdx.y, v = blockIdx.x, tid = threadIdx.x;
    if (tid == 0) {
        int c = 0, k = 0;
        for (int l = 0; l < NL; l++) {
            int n = g_cnt[dir][l];
            kb[l] = k; cb[l] = c;
            c += (n + CH - 1) / CH; k += n;
        }
        cb[NL] = c;
        if (v < c) {
            int l = 0;
            while (cb[l+1] <= v) l++;
            int ks = kb[l] + (v - cb[l]) * CH;
            int ke = kb[l] + g_cnt[dir][l];
            if (ke > ks + CH) ke = ks + CH;
            sl = l; sks = ks; ske = ke;
        } else sl = -1;
    }
    __syncthreads();
    if (sl < 0) return;
    int ks = sks, ke = ske;

    int w = tid >> 5, lane = tid & 31;
    int g = lane >> 2, t = lane & 3;
    int rowbase = (w & 3) * 16, colbase = (w >> 2) * 32;
    int t64 = tid & 63, g1 = tid >> 6;

    float4 dacc[4];
    #pragma unroll
    for (int j = 0; j < 4; j++) dacc[j] = make_float4(0.f, 0.f, 0.f, 0.f);
    float s1r = 0.f;
    const float* src = &g_sorted[dir][0];

    for (int kt = ks; kt < ke; kt += 128) {
        __syncthreads();
        // stage + tf32-round, zero-pad past label end
        for (int k = tid; k < 128*CC; k += 256) {
            int r = k >> 6, c = k & 63;
            float f = (kt + r < ke) ? src[(kt + r)*CC + c] : 0.f;
            xs[r*SPITCH + c] = f2tf(f);
        }
        __syncthreads();
        // S1 ride-along (zeros contribute nothing)
        #pragma unroll 4
        for (int j = g1; j < 128; j += 4) s1r += __uint_as_float(xs[j*SPITCH + t64]);
        // tensor SYRK: 16 k-steps of 8 pixels
        #pragma unroll
        for (int kk = 0; kk < 128; kk += 8) {
            unsigned a0 = xs[(kk + t    )*SPITCH + rowbase + g];
            unsigned a1 = xs[(kk + t    )*SPITCH + rowbase + g + 8];
            unsigned a2 = xs[(kk + t + 4)*SPITCH + rowbase + g];
            unsigned a3 = xs[(kk + t + 4)*SPITCH + rowbase + g + 8];
            #pragma unroll
            for (int j = 0; j < 4; j++) {
                unsigned b0 = xs[(kk + t    )*SPITCH + colbase + j*8 + g];
                unsigned b1 = xs[(kk + t + 4)*SPITCH + colbase + j*8 + g];
                mma_tf32(dacc[j], a0, a1, a2, a3, b0, b1);
            }
        }
    }
    // write C partials: warp owns 16x32 slab, thread holds (g,2t) pairs
    float* P = &g_p2[dir][v][0];
    #pragma unroll
    for (int j = 0; j < 4; j++) {
        int col = colbase + j*8 + 2*t;
        *(float2*)&P[(rowbase + g    )*CC + col] = make_float2(dacc[j].x, dacc[j].y);
        *(float2*)&P[(rowbase + g + 8)*CC + col] = make_float2(dacc[j].z, dacc[j].w);
    }
    s1p[g1][t64] = s1r;
    __syncthreads();
    if (tid < CC)
        g_p1[dir][v][tid] = s1p[0][tid] + s1p[1][tid] + s1p[2][tid] + s1p[3][tid];
}

// ================= 5. reduce =================
__global__ __launch_bounds__(256, 1) void reduce_kernel() {
    __shared__ int rs, re;
    int dir = blockIdx.x >> 3, l = blockIdx.x & 7, tid = threadIdx.x;
    int slice = blockIdx.y;                  // 4 slices of 1024 elems
    if (tid == 0) {
        int c = 0, cs0 = 0, n0 = 0;
        for (int ll = 0; ll < NL; ll++) {
            int n = g_cnt[dir][ll];
            int nc = (n + CH - 1) / CH;
            if (ll == l) { cs0 = c; n0 = nc; }
            c += nc;
        }
        rs = cs0; re = cs0 + n0;
    }
    __syncthreads();
    int a = rs, b = re;
    for (int e = slice*1024 + tid; e < slice*1024 + 1024; e += 256) {
        float s = 0.f;
        for (int v = a; v < b; v++) s += g_p2[dir][v][e];
        g_S2[dir][l][e] = s;
    }
    if (slice == 0 && tid < CC) {
        float s = 0.f;
        for (int v = a; v < b; v++) s += g_p1[dir][v][tid];
        g_S1[dir][l][tid] = s;
    }
}

// ---------------- 64x64x64 in-block matmul, 256 threads ----------------
__device__ __forceinline__ void mm64(float* __restrict__ C,
                                     const float* __restrict__ A,
                                     const float* __restrict__ B,
                                     int tid, int nsform) {
    int rr = tid >> 4, cr = tid & 15;
    float acc[4][4] = {};
    #pragma unroll 4
    for (int k = 0; k < 64; k += 4) {
        float4 a[4], b[4];
        #pragma unroll
        for (int r = 0; r < 4; r++) a[r] = *(const float4*)&A[(rr*4 + r)*64 + k];
        #pragma unroll
        for (int i = 0; i < 4; i++) b[i] = *(const float4*)&B[(k + i)*64 + cr*4];
        #pragma unroll
        for (int r = 0; r < 4; r++) {
            float4 ar = a[r];
            acc[r][0] += ar.x*b[0].x + ar.y*b[1].x + ar.z*b[2].x + ar.w*b[3].x;
            acc[r][1] += ar.x*b[0].y + ar.y*b[1].y + ar.z*b[2].y + ar.w*b[3].y;
            acc[r][2] += ar.x*b[0].z + ar.y*b[1].z + ar.z*b[2].z + ar.w*b[3].z;
            acc[r][3] += ar.x*b[0].w + ar.y*b[1].w + ar.z*b[2].w + ar.w*b[3].w;
        }
    }
    #pragma unroll
    for (int r = 0; r < 4; r++)
        #pragma unroll
        for (int c = 0; c < 4; c++) {
            float v = acc[r][c];
            if (nsform) v = ((rr*4 + r) == (cr*4 + c) ? 1.5f : 0.f) - 0.5f*v;
            C[(rr*4 + r)*64 + cr*4 + c] = v;
        }
}

// ============ 6. Newton-Schulz ============
__global__ __launch_bounds__(256, 1) void ns_kernel() {
    extern __shared__ float sm[];
    float *Yp = sm, *Zp = sm + 4096, *Wp = sm + 8192, *Vp = sm + 12288;
    int lab = blockIdx.x >> 1, which = blockIdx.x & 1;
    int tid = threadIdx.x;
    __shared__ float mu[CC], rowsum[CC], s_sh;

    int n = g_cnt[which][lab];
    float fn = (float)n;
    if (tid < CC) mu[tid] = g_S1[which][lab][tid] / fmaxf(fn, 1.f);
    __syncthreads();
    float div = (fn - 1.f == 0.f) ? 1e-5f : (fn - 1.f);
    for (int k = tid; k < 4096; k += 256) {
        int i = k >> 6, j = k & 63;
        float a = (g_S2[which][lab][k] - fn*mu[i]*mu[j]) / div;
        if (which == 0 && i == j) a += 1.f;
        Yp[k] = a;
    }
    __syncthreads();
    if (n <= 10) {
        for (int k = tid; k < 4096; k += 256)
            g_WC[which][lab][k] = ((k >> 6) == (k & 63)) ? 1.f : 0.f;
        if (tid < CC) g_mu[which][lab][tid] = mu[tid];
        return;
    }
    if (tid < CC) {
        float sr = 0.f;
        for (int j = 0; j < 64; j++) sr += fabsf(Yp[tid*64 + j]);
        rowsum[tid] = sr;
    }
    __syncthreads();
    if (tid == 0) {
        float m = 1e-10f;
        for (int i = 0; i < CC; i++) m = fmaxf(m, rowsum[i]);
        s_sh = m;
    }
    __syncthreads();
    float s = s_sh, inv_s = 1.f / s;
    for (int k = tid; k < 4096; k += 256) {
        Yp[k] *= inv_s;
        Zp[k] = ((k >> 6) == (k & 63)) ? 1.f : 0.f;
    }
    __syncthreads();
    for (int it = 0; it < NS_IT; it++) {
        mm64(Wp, Zp, Yp, tid, 1);
        __syncthreads();
        mm64(Vp, Yp, Wp, tid, 0);
        __syncthreads();
        mm64(Yp, Wp, Zp, tid, 0);
        __syncthreads();
        float* t = Yp; Yp = Vp; Vp = Zp; Zp = t;
    }
    float fac = (which == 0) ? rsqrtf(s) : sqrtf(s);
    const float* srcm = (which == 0) ? Zp : Yp;
    for (int k = tid; k < 4096; k += 256) g_WC[which][lab][k] = srcm[k] * fac;
    if (tid < CC) g_mu[which][lab][tid] = mu[tid];
}

// ============ 7. combine ============
__global__ __launch_bounds__(256, 1) void combine_kernel() {
    extern __shared__ float csm[];
    float* Co = csm; float* Wh = csm + 4096; float* Tt = csm + 8192;
    int lab = blockIdx.x, tid = threadIdx.x;
    for (int k = tid; k < 4096; k += 256) {
        Co[k] = g_WC[1][lab][k];
        Wh[k] = g_WC[0][lab][k];
    }
    __syncthreads();
    mm64(Tt, Co, Wh, tid, 0);
    __syncthreads();
    for (int k = tid; k < 4096; k += 256) g_T[lab][k] = Tt[k];
    if (tid < CC) {
        float b = g_mu[1][lab][tid];
        const float* Tr = &Tt[tid*64];
        #pragma unroll 8
        for (int q = 0; q < CC; q++) b -= Tr[q] * g_mu[0][lab][q];
        g_beta[lab][tid] = b;
    }
    if (tid == 0) {
        float nc = (float)g_cnt[0][lab], ns = (float)g_cnt[1][lab];
        g_valid[lab] = (nc > 10.f) && (ns > 10.f) && (nc < 100.f*ns) && (ns < 100.f*nc);
    }
}

// ============ 8. apply on sorted rows: ysort = T x + beta (or x if invalid) ============
__global__ __launch_bounds__(256, 2) void apply_kernel() {
    extern __shared__ float asmem[];
    float* T0 = asmem;            // 4096
    float* T1 = asmem + 4096;     // 4096
    __shared__ int lb[NL];
    __shared__ float bet[2][CC];
    __shared__ int labA, labB, vA, vB;
    int tid = threadIdx.x;
    int pos0 = blockIdx.x * 256;
    if (tid < NL) lb[tid] = g_lbase[0][tid];
    __syncthreads();
    if (tid == 0) {
        int la = 0, lz = 0;
        #pragma unroll
        for (int ll = 1; ll < NL; ll++) {
            if (pos0       >= lb[ll]) la = ll;
            if (pos0 + 255 >= lb[ll]) lz = ll;
        }
        labA = la; labB = lz;
        vA = g_valid[la]; vB = g_valid[lz];
    }
    __syncthreads();
    int la = labA, lz = labB;
    for (int k = tid; k < 4096; k += 256) T0[k] = g_T[la][k];
    if (lz != la)
        for (int k = tid; k < 4096; k += 256) T1[k] = g_T[lz][k];
    if (tid < CC) {
        bet[0][tid] = g_beta[la][tid];
        bet[1][tid] = g_beta[lz][tid];
    }
    __syncthreads();

    int pos = pos0 + tid;
    int l = 0;
    #pragma unroll
    for (int ll = 1; ll < NL; ll++) if (pos >= lb[ll]) l = ll;

    const float* xr = &g_sorted[0][(long)pos*CC];
    float x[CC];
    #pragma unroll
    for (int i = 0; i < 16; i++) {
        float4 v = *(const float4*)&xr[i*4];
        x[i*4] = v.x; x[i*4+1] = v.y; x[i*4+2] = v.z; x[i*4+3] = v.w;
    }
    float* yr = &g_ysort[(long)pos*CC];
    int sel = (l == la) ? 0 : 1;
    int valid = sel ? vB : vA;
    if (!valid) {
        #pragma unroll
        for (int i = 0; i < 16; i++)
            *(float4*)&yr[i*4] = *(const float4*)&xr[i*4];
        return;
    }
    const float* T  = sel ? T1 : T0;
    const float* bl = bet[sel];
    for (int c0 = 0; c0 < CC; c0 += 4) {
        float a0 = bl[c0], a1 = bl[c0+1], a2 = bl[c0+2], a3 = bl[c0+3];
        #pragma unroll
        for (int q = 0; q < CC; q += 4) {
            float4 t0 = *(const float4*)&T[(c0+0)*64 + q];
            float4 t1 = *(const float4*)&T[(c0+1)*64 + q];
            float4 t2 = *(const float4*)&T[(c0+2)*64 + q];
            float4 t3 = *(const float4*)&T[(c0+3)*64 + q];
            a0 += t0.x*x[q] + t0.y*x[q+1] + t0.z*x[q+2] + t0.w*x[q+3];
            a1 += t1.x*x[q] + t1.y*x[q+1] + t1.z*x[q+2] + t1.w*x[q+3];
            a2 += t2.x*x[q] + t2.y*x[q+1] + t2.z*x[q+2] + t2.w*x[q+3];
            a3 += t3.x*x[q] + t3.y*x[q+1] + t3.z*x[q+2] + t3.w*x[q+3];
        }
        *(float4*)&yr[c0] = make_float4(a0, a1, a2, a3);
    }
}

// ============ 9. writeout: gather sorted rows back to channel-major ============
__global__ __launch_bounds__(256, 2) void writeout_kernel(float* __restrict__ out) {
    int p = blockIdx.x*256 + threadIdx.x;
    int pos = g_posmap[p];
    const float* yr = &g_ysort[(long)pos*CC];
    float y[CC];
    #pragma unroll
    for (int i = 0; i < 16; i++) {
        float4 v = *(const float4*)&yr[i*4];
        y[i*4] = v.x; y[i*4+1] = v.y; y[i*4+2] = v.z; y[i*4+3] = v.w;
    }
    #pragma unroll
    for (int c = 0; c < CC; c++) out[c*NPIX + p] = y[c];
}

extern "C" void kernel_launch(void* const* d_in, const int* in_sizes, int n_in,
                              void* d_out, int out_size) {
    const float* cf = (const float*)d_in[0];
    const float* sf = (const float*)d_in[1];
    const int*   cs = (const int*)d_in[2];
    const int*   ss = (const int*)d_in[3];
    float* out = (float*)d_out;

    int scat_smem  = 256*65*4;      // 66560
    int ns_smem    = 4*4096*4;      // 65536
    int comb_smem  = 3*4096*4;      // 49152
    int apply_smem = 2*4096*4;      // 32768

    cudaFuncSetAttribute(scatter_kernel, cudaFuncAttributeMaxDynamicSharedMemorySize, scat_smem);
    cudaFuncSetAttribute(ns_kernel,      cudaFuncAttributeMaxDynamicSharedMemorySize, ns_smem);
    cudaFuncSetAttribute(combine_kernel, cudaFuncAttributeMaxDynamicSharedMemorySize, comb_smem);
    cudaFuncSetAttribute(apply_kernel,   cudaFuncAttributeMaxDynamicSharedMemorySize, apply_smem);

    hist_kernel<<<dim3(NBLK, 2), 256>>>(cs, ss);                        // 1
    scan_kernel<<<1, 256>>>();                                          // 2
    scatter_kernel<<<dim3(NBLK, 2), 256, scat_smem>>>(cf, sf, cs, ss);  // 3
    stats_kernel<<<dim3(MAXV, 2), 256>>>();                             // 4 (profiled)
    reduce_kernel<<<dim3(16, 4), 256>>>();                              // 5
    ns_kernel<<<16, 256, ns_smem>>>();                                  // 6
    combine_kernel<<<NL, 256, comb_smem>>>();                           // 7
    apply_kernel<<<NPIX/256, 256, apply_smem>>>();                      // 8
    writeout_kernel<<<NPIX/256, 256>>>(out);                            // 9
}